// round 12
// baseline (speedup 1.0000x reference)
#include <cuda_runtime.h>
#include <cuda_fp16.h>

#define GN 50000
#define GE 800000
#define EP 850000   // GE + GN self-loops
#define GG 64
#define NCH 98      // ceil(GN/512)

// ---------------- scratch (device globals; no allocation) ----------------
__device__ __align__(16) __half d_xl16[GN * 128];
__device__ __align__(16) float  d_xr[GN * 128];
__device__ __align__(16) float  d_h[GN * 128];
__device__ int   d_rowcnt[GN];
__device__ int   d_rowstart[GN + 1];
__device__ int   d_rowfill[GN];
__device__ int   d_csrsrc[EP];
__device__ int   d_chunksum[NCH];
__device__ float d_pool[GG * 128];
__device__ float d_cnt[GG];
__device__ int   d_is64;

__device__ __forceinline__ int edge_at(const void* ei, int idx, int is64) {
    return is64 ? (int)((const long long*)ei)[idx] : ((const int*)ei)[idx];
}

// ---------------- fused init: width detect + all zeroing ----------------
__global__ void init_kernel(const int* __restrict__ ei32) {
    int i = blockIdx.x * blockDim.x + threadIdx.x;
    if (i == 0) {
        int any = 0;
        #pragma unroll
        for (int k = 1; k < 128; k += 2) any |= ei32[k];
        d_is64 = (any == 0) ? 1 : 0;
    }
    if (i < GN) d_rowcnt[i] = 0;
    if (i < GG * 128) d_pool[i] = 0.f;
    if (i < GG) d_cnt[i] = 0.f;
}

// ---------------- CSR build: hist -> scan -> scatter ----------------
__global__ void hist_kernel(const void* __restrict__ ei) {
    int i = blockIdx.x * blockDim.x + threadIdx.x;
    if (i >= EP) return;
    int is64 = d_is64;
    int dd = (i < GE) ? edge_at(ei, GE + i, is64) : (i - GE);
    atomicAdd(&d_rowcnt[dd], 1);
}

__global__ void chunk_sum_kernel() {
    __shared__ int sh[256];
    int b = blockIdx.x, t = threadIdx.x;
    int base = b * 512;
    int v = 0;
    int i0 = base + t;       if (i0 < GN) v += d_rowcnt[i0];
    int i1 = base + 256 + t; if (i1 < GN) v += d_rowcnt[i1];
    sh[t] = v; __syncthreads();
    for (int off = 128; off; off >>= 1) {
        if (t < off) sh[t] += sh[t + off];
        __syncthreads();
    }
    if (t == 0) d_chunksum[b] = sh[0];
}

__global__ void tops_kernel() {
    __shared__ int sh[128];
    int t = threadIdx.x;
    int v = (t < NCH) ? d_chunksum[t] : 0;
    sh[t] = v; __syncthreads();
    for (int off = 1; off < 128; off <<= 1) {
        int a = (t >= off) ? sh[t - off] : 0;
        __syncthreads();
        sh[t] += a;
        __syncthreads();
    }
    if (t < NCH) d_chunksum[t] = sh[t] - v;   // exclusive
    if (t == 0) d_rowstart[GN] = EP;
}

__global__ void scan_apply_kernel() {
    __shared__ int sh[512];
    int b = blockIdx.x, t = threadIdx.x;
    int i = b * 512 + t;
    int v = (i < GN) ? d_rowcnt[i] : 0;
    sh[t] = v; __syncthreads();
    for (int off = 1; off < 512; off <<= 1) {
        int a = (t >= off) ? sh[t - off] : 0;
        __syncthreads();
        sh[t] += a;
        __syncthreads();
    }
    if (i < GN) {
        int excl = sh[t] - v + d_chunksum[b];
        d_rowstart[i] = excl;
        d_rowfill[i]  = excl;
    }
}

__global__ void scatter_kernel(const void* __restrict__ ei) {
    int i = blockIdx.x * blockDim.x + threadIdx.x;
    if (i >= EP) return;
    int is64 = d_is64;
    int ss, dd;
    if (i < GE) { ss = edge_at(ei, i, is64); dd = edge_at(ei, GE + i, is64); }
    else        { ss = i - GE; dd = ss; }
    int pos = atomicAdd(&d_rowfill[dd], 1);
    d_csrsrc[pos] = ss;
}

// ---------------- tf32x3 tensor-core GEMM (64x128 tile, low regs) -------
__device__ __forceinline__ void tf32_split(float x, float& hi, float& lo) {
    unsigned u;
    asm("cvt.rna.tf32.f32 %0, %1;" : "=r"(u) : "f"(x));
    hi = __uint_as_float(u);
    float r = x - hi;
    unsigned v;
    asm("cvt.rna.tf32.f32 %0, %1;" : "=r"(v) : "f"(r));
    lo = __uint_as_float(v);
}

__device__ __forceinline__ void mma_tf32(float* c,
                                         float a0, float a1, float a2, float a3,
                                         float b0, float b1) {
    asm("mma.sync.aligned.m16n8k8.row.col.f32.tf32.tf32.f32 "
        "{%0,%1,%2,%3}, {%4,%5,%6,%7}, {%8,%9}, {%0,%1,%2,%3};"
        : "+f"(c[0]), "+f"(c[1]), "+f"(c[2]), "+f"(c[3])
        : "r"(__float_as_uint(a0)), "r"(__float_as_uint(a1)),
          "r"(__float_as_uint(a2)), "r"(__float_as_uint(a3)),
          "r"(__float_as_uint(b0)), "r"(__float_as_uint(b1)));
}

#define SPA 72    // A smem pitch (floats), 72 % 32 == 8 -> conflict-free frags
#define SPB 136   // B smem pitch

__global__ void __launch_bounds__(256) gemm_kernel(
    const float* __restrict__ x_in,
    const float* __restrict__ Wl, const float* __restrict__ bl,
    const float* __restrict__ Wr, const float* __restrict__ br,
    int use_h)
{
    const float* A = use_h ? d_h : x_in;
    int mat = blockIdx.y;
    const float* W    = mat ? Wr : Wl;
    const float* bias = mat ? br : bl;
    int row0 = blockIdx.x * 64;

    __shared__ float As_hi[2][8 * SPA];
    __shared__ float As_lo[2][8 * SPA];
    __shared__ float Bs_hi[2][8 * SPB];
    __shared__ float Bs_lo[2][8 * SPB];

    int tid  = threadIdx.x;
    int w    = tid >> 5;
    int lane = tid & 31;
    int g    = lane >> 2;
    int t4   = lane & 3;
    int rw   = (w & 3) * 16;   // warp row base (16-row m tile)
    int cw   = (w >> 2) * 64;  // warp col base

    int ar = tid >> 2;         // A row 0..63
    int ak = (tid & 3) * 2;    // A k-pair base
    int wr = tid >> 1;         // W col 0..127
    int wk = (tid & 1) * 4;    // W k-quad base

    bool okA = (row0 + ar) < GN;
    const float* Aptr = A + (size_t)(row0 + ar) * 128 + ak;
    const float* Wptr = W + (size_t)wr * 128 + wk;

    float acc[8][4];
    #pragma unroll
    for (int n = 0; n < 8; n++)
        #pragma unroll
        for (int q = 0; q < 4; q++) acc[n][q] = 0.f;

    // stage chunk 0 into buffer 0
    {
        float2 av = okA ? *(const float2*)Aptr : make_float2(0.f, 0.f);
        float4 wv = *(const float4*)Wptr;
        float h0, l0, h1, l1;
        tf32_split(av.x, h0, l0); tf32_split(av.y, h1, l1);
        As_hi[0][(ak + 0) * SPA + ar] = h0;
        As_lo[0][(ak + 0) * SPA + ar] = l0;
        As_hi[0][(ak + 1) * SPA + ar] = h1;
        As_lo[0][(ak + 1) * SPA + ar] = l1;
        float wh[4], wl[4];
        tf32_split(wv.x, wh[0], wl[0]); tf32_split(wv.y, wh[1], wl[1]);
        tf32_split(wv.z, wh[2], wl[2]); tf32_split(wv.w, wh[3], wl[3]);
        #pragma unroll
        for (int m = 0; m < 4; m++) {
            Bs_hi[0][(wk + m) * SPB + wr] = wh[m];
            Bs_lo[0][(wk + m) * SPB + wr] = wl[m];
        }
    }
    __syncthreads();

    for (int kc = 0; kc < 16; kc++) {
        int p = kc & 1;

        float2 av; float4 wv;
        if (kc < 15) {
            av = okA ? *(const float2*)(Aptr + (kc + 1) * 8) : make_float2(0.f, 0.f);
            wv = *(const float4*)(Wptr + (kc + 1) * 8);
        }

        float Ah[4], Al[4];
        Ah[0] = As_hi[p][t4 * SPA + rw + g];
        Ah[1] = As_hi[p][t4 * SPA + rw + g + 8];
        Ah[2] = As_hi[p][(t4 + 4) * SPA + rw + g];
        Ah[3] = As_hi[p][(t4 + 4) * SPA + rw + g + 8];
        Al[0] = As_lo[p][t4 * SPA + rw + g];
        Al[1] = As_lo[p][t4 * SPA + rw + g + 8];
        Al[2] = As_lo[p][(t4 + 4) * SPA + rw + g];
        Al[3] = As_lo[p][(t4 + 4) * SPA + rw + g + 8];

        #pragma unroll
        for (int n = 0; n < 8; n++) {
            int cb = cw + n * 8;
            float bh0 = Bs_hi[p][t4 * SPB + cb + g];
            float bh1 = Bs_hi[p][(t4 + 4) * SPB + cb + g];
            float bl0 = Bs_lo[p][t4 * SPB + cb + g];
            float bl1 = Bs_lo[p][(t4 + 4) * SPB + cb + g];
            mma_tf32(acc[n], Ah[0], Ah[1], Ah[2], Ah[3], bh0, bh1);
            mma_tf32(acc[n], Ah[0], Ah[1], Ah[2], Ah[3], bl0, bl1);
            mma_tf32(acc[n], Al[0], Al[1], Al[2], Al[3], bh0, bh1);
        }

        if (kc < 15) {
            float h0, l0, h1, l1;
            tf32_split(av.x, h0, l0); tf32_split(av.y, h1, l1);
            float wh[4], wl[4];
            tf32_split(wv.x, wh[0], wl[0]); tf32_split(wv.y, wh[1], wl[1]);
            tf32_split(wv.z, wh[2], wl[2]); tf32_split(wv.w, wh[3], wl[3]);
            int q = 1 - p;
            As_hi[q][(ak + 0) * SPA + ar] = h0;
            As_lo[q][(ak + 0) * SPA + ar] = l0;
            As_hi[q][(ak + 1) * SPA + ar] = h1;
            As_lo[q][(ak + 1) * SPA + ar] = l1;
            #pragma unroll
            for (int m = 0; m < 4; m++) {
                Bs_hi[q][(wk + m) * SPB + wr] = wh[m];
                Bs_lo[q][(wk + m) * SPB + wr] = wl[m];
            }
            __syncthreads();
        }
    }

    int r0 = row0 + rw + g;
    int r1 = r0 + 8;
    #pragma unroll
    for (int n = 0; n < 8; n++) {
        int cb = cw + n * 8 + t4 * 2;
        float b0 = bias[cb], b1 = bias[cb + 1];
        float v00 = acc[n][0] + b0, v01 = acc[n][1] + b1;
        float v10 = acc[n][2] + b0, v11 = acc[n][3] + b1;
        if (mat == 0) {
            if (r0 < GN)
                *(__half2*)&d_xl16[(size_t)r0 * 128 + cb] = __floats2half2_rn(v00, v01);
            if (r1 < GN)
                *(__half2*)&d_xl16[(size_t)r1 * 128 + cb] = __floats2half2_rn(v10, v11);
        } else {
            if (r0 < GN)
                *(float2*)&d_xr[(size_t)r0 * 128 + cb] = make_float2(v00, v01);
            if (r1 < GN)
                *(float2*)&d_xr[(size_t)r1 * 128 + cb] = make_float2(v10, v11);
        }
    }
}

// ---------------- fused GATv2 (two warps per row, fp16 xl) --------------
__device__ __forceinline__ float4 xl_load(const uint2* __restrict__ XL16,
                                          int s, int lane) {
    uint2 v = XL16[(size_t)s * 32 + lane];
    float2 f01 = __half22float2(*(__half2*)&v.x);
    float2 f23 = __half22float2(*(__half2*)&v.y);
    return make_float4(f01.x, f01.y, f23.x, f23.y);
}

__device__ __forceinline__ float edge_logit(const float4& xv, const float4& xrv,
                                            const float4& attv) {
    float v, lg;
    v = xv.x + xrv.x; v = v > 0.f ? v : 0.2f * v; lg = v * attv.x;
    v = xv.y + xrv.y; v = v > 0.f ? v : 0.2f * v; lg = fmaf(v, attv.y, lg);
    v = xv.z + xrv.z; v = v > 0.f ? v : 0.2f * v; lg = fmaf(v, attv.z, lg);
    v = xv.w + xrv.w; v = v > 0.f ? v : 0.2f * v; lg = fmaf(v, attv.w, lg);
    return lg;
}

__device__ __forceinline__ void gat_half(const uint2* XL16, int s0, int s1,
                                         int lane, const float4& xrv,
                                         const float4& attv,
                                         float& mx, float& dn, float4& ac)
{
    mx = -1e30f; dn = 0.f;
    ac = make_float4(0.f, 0.f, 0.f, 0.f);
    int cnt = s1 - s0;

    float4 xv0, xv1, xv2, xv3;
    if (cnt >= 4) {
        xv0 = xl_load(XL16, d_csrsrc[s0],     lane);
        xv1 = xl_load(XL16, d_csrsrc[s0 + 1], lane);
        xv2 = xl_load(XL16, d_csrsrc[s0 + 2], lane);
        xv3 = xl_load(XL16, d_csrsrc[s0 + 3], lane);
    }

    int j = s0;
    for (; j + 3 < s1; j += 4) {
        int p0 = (j + 4 < s1) ? d_csrsrc[j + 4] : 0;
        int p1 = (j + 5 < s1) ? d_csrsrc[j + 5] : 0;
        int p2 = (j + 6 < s1) ? d_csrsrc[j + 6] : 0;
        int p3 = (j + 7 < s1) ? d_csrsrc[j + 7] : 0;
        float4 xn0 = xl_load(XL16, p0, lane);
        float4 xn1 = xl_load(XL16, p1, lane);
        float4 xn2 = xl_load(XL16, p2, lane);
        float4 xn3 = xl_load(XL16, p3, lane);

        float lg0 = edge_logit(xv0, xrv, attv);
        float lg1 = edge_logit(xv1, xrv, attv);
        float lg2 = edge_logit(xv2, xrv, attv);
        float lg3 = edge_logit(xv3, xrv, attv);
        lg0 += __shfl_xor_sync(0xffffffffu, lg0, 4);
        lg1 += __shfl_xor_sync(0xffffffffu, lg1, 4);
        lg2 += __shfl_xor_sync(0xffffffffu, lg2, 4);
        lg3 += __shfl_xor_sync(0xffffffffu, lg3, 4);
        lg0 += __shfl_xor_sync(0xffffffffu, lg0, 2);
        lg1 += __shfl_xor_sync(0xffffffffu, lg1, 2);
        lg2 += __shfl_xor_sync(0xffffffffu, lg2, 2);
        lg3 += __shfl_xor_sync(0xffffffffu, lg3, 2);
        lg0 += __shfl_xor_sync(0xffffffffu, lg0, 1);
        lg1 += __shfl_xor_sync(0xffffffffu, lg1, 1);
        lg2 += __shfl_xor_sync(0xffffffffu, lg2, 1);
        lg3 += __shfl_xor_sync(0xffffffffu, lg3, 1);

        float m = fmaxf(fmaxf(lg0, lg1), fmaxf(lg2, lg3));
        float w0 = __expf(lg0 - m);
        float w1 = __expf(lg1 - m);
        float w2 = __expf(lg2 - m);
        float w3 = __expf(lg3 - m);
        float pd = (w0 + w1) + (w2 + w3);
        float4 pa;
        pa.x = fmaf(w0, xv0.x, w1 * xv1.x) + fmaf(w2, xv2.x, w3 * xv3.x);
        pa.y = fmaf(w0, xv0.y, w1 * xv1.y) + fmaf(w2, xv2.y, w3 * xv3.y);
        pa.z = fmaf(w0, xv0.z, w1 * xv1.z) + fmaf(w2, xv2.z, w3 * xv3.z);
        pa.w = fmaf(w0, xv0.w, w1 * xv1.w) + fmaf(w2, xv2.w, w3 * xv3.w);

        float nm = fmaxf(mx, m);
        float a  = __expf(mx - nm);
        float b  = __expf(m - nm);
        dn = fmaf(dn, a, pd * b);
        ac.x = fmaf(ac.x, a, pa.x * b);
        ac.y = fmaf(ac.y, a, pa.y * b);
        ac.z = fmaf(ac.z, a, pa.z * b);
        ac.w = fmaf(ac.w, a, pa.w * b);
        mx = nm;

        xv0 = xn0; xv1 = xn1; xv2 = xn2; xv3 = xn3;
    }

    for (; j < s1; j++) {
        float4 xv = xl_load(XL16, d_csrsrc[j], lane);
        float lg = edge_logit(xv, xrv, attv);
        lg += __shfl_xor_sync(0xffffffffu, lg, 4);
        lg += __shfl_xor_sync(0xffffffffu, lg, 2);
        lg += __shfl_xor_sync(0xffffffffu, lg, 1);
        float nm = fmaxf(mx, lg);
        float a  = __expf(mx - nm);
        float w  = __expf(lg - nm);
        dn = fmaf(dn, a, w);
        ac.x = fmaf(ac.x, a, w * xv.x);
        ac.y = fmaf(ac.y, a, w * xv.y);
        ac.z = fmaf(ac.z, a, w * xv.z);
        ac.w = fmaf(ac.w, a, w * xv.w);
        mx = nm;
    }
}

__global__ void __launch_bounds__(256) gat_row_kernel(const float* __restrict__ att,
                                                      const float* __restrict__ bias)
{
    __shared__ float s_mx[4][32], s_dn[4][32];
    __shared__ float s_ac[4][4][32];

    int w    = threadIdx.x >> 5;
    int lane = threadIdx.x & 31;
    int ridx = w >> 1;
    int half = w & 1;
    int row  = blockIdx.x * 4 + ridx;
    if (row >= GN) return;

    float4 attv = ((const float4*)att)[lane];
    float4 xrv  = ((const float4*)d_xr)[(size_t)row * 32 + lane];

    int e0 = d_rowstart[row], e1 = d_rowstart[row + 1];
    int mid = e0 + ((e1 - e0 + 1) >> 1);
    int s0 = half ? mid : e0;
    int s1 = half ? e1  : mid;

    const uint2* XL16 = (const uint2*)d_xl16;

    float mx, dn; float4 ac;
    gat_half(XL16, s0, s1, lane, xrv, attv, mx, dn, ac);

    if (half) {
        s_mx[ridx][lane] = mx;
        s_dn[ridx][lane] = dn;
        s_ac[ridx][0][lane] = ac.x;
        s_ac[ridx][1][lane] = ac.y;
        s_ac[ridx][2][lane] = ac.z;
        s_ac[ridx][3][lane] = ac.w;
    }
    __syncthreads();
    if (half) return;

    float mxB = s_mx[ridx][lane];
    float dnB = s_dn[ridx][lane];
    float nm = fmaxf(mx, mxB);
    float a  = __expf(mx - nm);
    float b  = __expf(mxB - nm);
    float dnT = fmaf(dn, a, dnB * b);
    float4 acT;
    acT.x = fmaf(ac.x, a, s_ac[ridx][0][lane] * b);
    acT.y = fmaf(ac.y, a, s_ac[ridx][1][lane] * b);
    acT.z = fmaf(ac.z, a, s_ac[ridx][2][lane] * b);
    acT.w = fmaf(ac.w, a, s_ac[ridx][3][lane] * b);

    float inv = 1.f / dnT;
    float4 bv = ((const float4*)bias)[lane];
    float4 o;
    o.x = fmaxf(fmaf(acT.x, inv, bv.x), 0.f);
    o.y = fmaxf(fmaf(acT.y, inv, bv.y), 0.f);
    o.z = fmaxf(fmaf(acT.z, inv, bv.z), 0.f);
    o.w = fmaxf(fmaf(acT.w, inv, bv.w), 0.f);
    ((float4*)d_h)[(size_t)row * 32 + lane] = o;
}

// ---------------- pooling (count folded into pool) ----------------------
__global__ void pool_kernel(const void* __restrict__ batch) {
    const int CHUNK = 256;
    int n0 = blockIdx.x * CHUNK;
    int n1 = n0 + CHUNK; if (n1 > GN) n1 = GN;
    int col = threadIdx.x;
    int is64 = d_is64;
    int curg = -1;
    float acc = 0.f;
    int run = 0;
    for (int n = n0; n < n1; n++) {
        int g = edge_at(batch, n, is64);
        if (g != curg) {
            if (curg >= 0) {
                atomicAdd(&d_pool[curg * 128 + col], acc);
                if (col == 0) atomicAdd(&d_cnt[curg], (float)run);
            }
            curg = g; acc = 0.f; run = 0;
        }
        acc += d_h[(size_t)n * 128 + col];
        run++;
    }
    if (curg >= 0) {
        atomicAdd(&d_pool[curg * 128 + col], acc);
        if (col == 0) atomicAdd(&d_cnt[curg], (float)run);
    }
}

// ---------------- classifier ----------------
__global__ void classifier_kernel(
    const float* __restrict__ Wc1, const float* __restrict__ bc1,
    const float* __restrict__ Wc2, const float* __restrict__ bc2,
    float* __restrict__ out)
{
    int g = threadIdx.x;
    if (g >= GG) return;
    float inv = 1.f / fmaxf(d_cnt[g], 1.f);
    float z[8];
    #pragma unroll
    for (int j = 0; j < 8; j++) {
        float s = 0.f;
        for (int k = 0; k < 128; k++)
            s += d_pool[g * 128 + k] * Wc1[j * 128 + k];
        s = s * inv + bc1[j];
        z[j] = fmaxf(s, 0.f);
    }
    float o = bc2[0];
    #pragma unroll
    for (int j = 0; j < 8; j++) o += z[j] * Wc2[j];
    out[g] = o;
}

// ---------------- launch ----------------
extern "C" void kernel_launch(void* const* d_in, const int* in_sizes, int n_in,
                              void* d_out, int out_size) {
    const float* x     = (const float*)d_in[0];
    const void*  ei    = d_in[1];
    const void*  batch = d_in[2];
    const float* Wl0 = (const float*)d_in[3];
    const float* bl0 = (const float*)d_in[4];
    const float* Wr0 = (const float*)d_in[5];
    const float* br0 = (const float*)d_in[6];
    const float* at0 = (const float*)d_in[7];
    const float* bi0 = (const float*)d_in[8];
    const float* Wl1 = (const float*)d_in[9];
    const float* bl1 = (const float*)d_in[10];
    const float* Wr1 = (const float*)d_in[11];
    const float* br1 = (const float*)d_in[12];
    const float* at1 = (const float*)d_in[13];
    const float* bi1 = (const float*)d_in[14];
    const float* Wc1 = (const float*)d_in[15];
    const float* bc1 = (const float*)d_in[16];
    const float* Wc2 = (const float*)d_in[17];
    const float* bc2 = (const float*)d_in[18];
    float* out = (float*)d_out;

    const dim3 GEMM_GRID((GN + 63) / 64, 2);

    init_kernel<<<(GN + 255) / 256, 256>>>((const int*)ei);    // 1
    hist_kernel<<<(EP + 255) / 256, 256>>>(ei);                // 2
    chunk_sum_kernel<<<NCH, 256>>>();                          // 3
    gemm_kernel<<<GEMM_GRID, 256>>>(x, Wl0, bl0, Wr0, br0, 0); // 4 (profiled)
    tops_kernel<<<1, 128>>>();                                 // 5
    scan_apply_kernel<<<NCH, 512>>>();                         // 6
    scatter_kernel<<<(EP + 255) / 256, 256>>>(ei);             // 7

    gat_row_kernel<<<(GN + 3) / 4, 256>>>(at0, bi0);           // 8
    gemm_kernel<<<GEMM_GRID, 256>>>(x, Wl1, bl1, Wr1, br1, 1); // 9
    gat_row_kernel<<<(GN + 3) / 4, 256>>>(at1, bi1);           // 10

    pool_kernel<<<(GN + 255) / 256, 128>>>(batch);             // 11
    classifier_kernel<<<1, 64>>>(Wc1, bc1, Wc2, bc2, out);     // 12
}

// round 13
// speedup vs baseline: 1.0864x; 1.0864x over previous
#include <cuda_runtime.h>
#include <cuda_fp16.h>

#define GN 50000
#define GE 800000
#define EP 850000   // GE + GN self-loops
#define GG 64
#define NCH 98      // ceil(GN/512)

// ---------------- scratch (device globals; no allocation) ----------------
__device__ __align__(16) __half d_xl16[GN * 128];
__device__ __align__(16) float  d_xr[GN * 128];
__device__ __align__(16) float  d_h[GN * 128];
__device__ int   d_rowcnt[GN];
__device__ int   d_rowstart[GN + 1];
__device__ int   d_rowfill[GN];
__device__ int   d_csrsrc[EP];
__device__ int   d_chunksum[NCH];
__device__ float d_pool[GG * 128];
__device__ float d_cnt[GG];
__device__ int   d_is64;

__device__ __forceinline__ int edge_at(const void* ei, int idx, int is64) {
    return is64 ? (int)((const long long*)ei)[idx] : ((const int*)ei)[idx];
}

// ---------------- side stream + events (created once, before tracking) ---
struct StreamHolder {
    cudaStream_t s = nullptr;
    cudaEvent_t evFork = nullptr, evJoin = nullptr;
    StreamHolder() { init(); }
    void init() {
        if (!s) {
            cudaStreamCreateWithFlags(&s, cudaStreamNonBlocking);
            cudaEventCreateWithFlags(&evFork, cudaEventDisableTiming);
            cudaEventCreateWithFlags(&evJoin, cudaEventDisableTiming);
        }
    }
};
static StreamHolder g_sh;

// ---------------- fused init: width detect + all zeroing ----------------
__global__ void init_kernel(const int* __restrict__ ei32) {
    int i = blockIdx.x * blockDim.x + threadIdx.x;
    if (i == 0) {
        int any = 0;
        #pragma unroll
        for (int k = 1; k < 128; k += 2) any |= ei32[k];
        d_is64 = (any == 0) ? 1 : 0;
    }
    if (i < GN) d_rowcnt[i] = 0;
    if (i < GG * 128) d_pool[i] = 0.f;
    if (i < GG) d_cnt[i] = 0.f;
}

// ---------------- CSR build: hist -> scan -> scatter ----------------
__global__ void hist_kernel(const void* __restrict__ ei) {
    int i = blockIdx.x * blockDim.x + threadIdx.x;
    if (i >= EP) return;
    int is64 = d_is64;
    int dd = (i < GE) ? edge_at(ei, GE + i, is64) : (i - GE);
    atomicAdd(&d_rowcnt[dd], 1);
}

__global__ void chunk_sum_kernel() {
    __shared__ int sh[256];
    int b = blockIdx.x, t = threadIdx.x;
    int base = b * 512;
    int v = 0;
    int i0 = base + t;       if (i0 < GN) v += d_rowcnt[i0];
    int i1 = base + 256 + t; if (i1 < GN) v += d_rowcnt[i1];
    sh[t] = v; __syncthreads();
    for (int off = 128; off; off >>= 1) {
        if (t < off) sh[t] += sh[t + off];
        __syncthreads();
    }
    if (t == 0) d_chunksum[b] = sh[0];
}

__global__ void tops_kernel() {
    __shared__ int sh[128];
    int t = threadIdx.x;
    int v = (t < NCH) ? d_chunksum[t] : 0;
    sh[t] = v; __syncthreads();
    for (int off = 1; off < 128; off <<= 1) {
        int a = (t >= off) ? sh[t - off] : 0;
        __syncthreads();
        sh[t] += a;
        __syncthreads();
    }
    if (t < NCH) d_chunksum[t] = sh[t] - v;   // exclusive
    if (t == 0) d_rowstart[GN] = EP;
}

__global__ void scan_apply_kernel() {
    __shared__ int sh[512];
    int b = blockIdx.x, t = threadIdx.x;
    int i = b * 512 + t;
    int v = (i < GN) ? d_rowcnt[i] : 0;
    sh[t] = v; __syncthreads();
    for (int off = 1; off < 512; off <<= 1) {
        int a = (t >= off) ? sh[t - off] : 0;
        __syncthreads();
        sh[t] += a;
        __syncthreads();
    }
    if (i < GN) {
        int excl = sh[t] - v + d_chunksum[b];
        d_rowstart[i] = excl;
        d_rowfill[i]  = excl;
    }
}

__global__ void scatter_kernel(const void* __restrict__ ei) {
    int i = blockIdx.x * blockDim.x + threadIdx.x;
    if (i >= EP) return;
    int is64 = d_is64;
    int ss, dd;
    if (i < GE) { ss = edge_at(ei, i, is64); dd = edge_at(ei, GE + i, is64); }
    else        { ss = i - GE; dd = ss; }
    int pos = atomicAdd(&d_rowfill[dd], 1);
    d_csrsrc[pos] = ss;
}

// ---------------- tf32x3 tensor-core GEMM (128x128 tile, R11 version) ---
__device__ __forceinline__ void tf32_split(float x, float& hi, float& lo) {
    unsigned u;
    asm("cvt.rna.tf32.f32 %0, %1;" : "=r"(u) : "f"(x));
    hi = __uint_as_float(u);
    float r = x - hi;
    unsigned v;
    asm("cvt.rna.tf32.f32 %0, %1;" : "=r"(v) : "f"(r));
    lo = __uint_as_float(v);
}

__device__ __forceinline__ void mma_tf32(float* c,
                                         float a0, float a1, float a2, float a3,
                                         float b0, float b1) {
    asm("mma.sync.aligned.m16n8k8.row.col.f32.tf32.tf32.f32 "
        "{%0,%1,%2,%3}, {%4,%5,%6,%7}, {%8,%9}, {%0,%1,%2,%3};"
        : "+f"(c[0]), "+f"(c[1]), "+f"(c[2]), "+f"(c[3])
        : "r"(__float_as_uint(a0)), "r"(__float_as_uint(a1)),
          "r"(__float_as_uint(a2)), "r"(__float_as_uint(a3)),
          "r"(__float_as_uint(b0)), "r"(__float_as_uint(b1)));
}

#define SP 136   // smem pitch (floats)

__global__ void __launch_bounds__(256) gemm_kernel(
    const float* __restrict__ x_in,
    const float* __restrict__ Wl, const float* __restrict__ bl,
    const float* __restrict__ Wr, const float* __restrict__ br,
    int use_h)
{
    const float* A = use_h ? d_h : x_in;
    int mat = blockIdx.y;
    const float* W    = mat ? Wr : Wl;
    const float* bias = mat ? br : bl;
    int row0 = blockIdx.x * 128;

    __shared__ float As_hi[2][8 * SP];
    __shared__ float As_lo[2][8 * SP];
    __shared__ float Bs_hi[2][8 * SP];
    __shared__ float Bs_lo[2][8 * SP];

    int tid  = threadIdx.x;
    int w    = tid >> 5;
    int lane = tid & 31;
    int g    = lane >> 2;
    int t4   = lane & 3;
    int rw   = (w & 3) * 32;
    int cw   = (w >> 2) * 64;

    int lrow = tid >> 1;
    int lq   = tid & 1;

    bool okA = (row0 + lrow) < GN;
    const float* Aptr = A + (size_t)(row0 + lrow) * 128 + lq * 4;
    const float* Wptr = W + (size_t)lrow * 128 + lq * 4;

    float acc[2][8][4];
    #pragma unroll
    for (int m = 0; m < 2; m++)
        #pragma unroll
        for (int n = 0; n < 8; n++)
            #pragma unroll
            for (int q = 0; q < 4; q++) acc[m][n][q] = 0.f;

    {
        float4 av = okA ? *(const float4*)Aptr : make_float4(0.f, 0.f, 0.f, 0.f);
        float4 wv = *(const float4*)Wptr;
        float ah[4], al[4], wh[4], wl[4];
        tf32_split(av.x, ah[0], al[0]); tf32_split(av.y, ah[1], al[1]);
        tf32_split(av.z, ah[2], al[2]); tf32_split(av.w, ah[3], al[3]);
        tf32_split(wv.x, wh[0], wl[0]); tf32_split(wv.y, wh[1], wl[1]);
        tf32_split(wv.z, wh[2], wl[2]); tf32_split(wv.w, wh[3], wl[3]);
        #pragma unroll
        for (int m = 0; m < 4; m++) {
            int k = lq * 4 + m;
            As_hi[0][k * SP + lrow] = ah[m];
            As_lo[0][k * SP + lrow] = al[m];
            Bs_hi[0][k * SP + lrow] = wh[m];
            Bs_lo[0][k * SP + lrow] = wl[m];
        }
    }
    __syncthreads();

    for (int kc = 0; kc < 16; kc++) {
        int p = kc & 1;

        float4 av, wv;
        if (kc < 15) {
            av = okA ? *(const float4*)(Aptr + (kc + 1) * 8)
                     : make_float4(0.f, 0.f, 0.f, 0.f);
            wv = *(const float4*)(Wptr + (kc + 1) * 8);
        }

        float Ah[2][4], Al[2][4];
        #pragma unroll
        for (int m = 0; m < 2; m++) {
            int rb = rw + m * 16;
            Ah[m][0] = As_hi[p][t4 * SP + rb + g];
            Ah[m][1] = As_hi[p][t4 * SP + rb + g + 8];
            Ah[m][2] = As_hi[p][(t4 + 4) * SP + rb + g];
            Ah[m][3] = As_hi[p][(t4 + 4) * SP + rb + g + 8];
            Al[m][0] = As_lo[p][t4 * SP + rb + g];
            Al[m][1] = As_lo[p][t4 * SP + rb + g + 8];
            Al[m][2] = As_lo[p][(t4 + 4) * SP + rb + g];
            Al[m][3] = As_lo[p][(t4 + 4) * SP + rb + g + 8];
        }

        #pragma unroll
        for (int n = 0; n < 8; n++) {
            int cb = cw + n * 8;
            float bh0 = Bs_hi[p][t4 * SP + cb + g];
            float bh1 = Bs_hi[p][(t4 + 4) * SP + cb + g];
            float bl0 = Bs_lo[p][t4 * SP + cb + g];
            float bl1 = Bs_lo[p][(t4 + 4) * SP + cb + g];
            #pragma unroll
            for (int m = 0; m < 2; m++) {
                mma_tf32(acc[m][n], Ah[m][0], Ah[m][1], Ah[m][2], Ah[m][3], bh0, bh1);
                mma_tf32(acc[m][n], Ah[m][0], Ah[m][1], Ah[m][2], Ah[m][3], bl0, bl1);
                mma_tf32(acc[m][n], Al[m][0], Al[m][1], Al[m][2], Al[m][3], bh0, bh1);
            }
        }

        if (kc < 15) {
            float ah[4], al[4], wh[4], wl[4];
            tf32_split(av.x, ah[0], al[0]); tf32_split(av.y, ah[1], al[1]);
            tf32_split(av.z, ah[2], al[2]); tf32_split(av.w, ah[3], al[3]);
            tf32_split(wv.x, wh[0], wl[0]); tf32_split(wv.y, wh[1], wl[1]);
            tf32_split(wv.z, wh[2], wl[2]); tf32_split(wv.w, wh[3], wl[3]);
            int q = 1 - p;
            #pragma unroll
            for (int m = 0; m < 4; m++) {
                int k = lq * 4 + m;
                As_hi[q][k * SP + lrow] = ah[m];
                As_lo[q][k * SP + lrow] = al[m];
                Bs_hi[q][k * SP + lrow] = wh[m];
                Bs_lo[q][k * SP + lrow] = wl[m];
            }
            __syncthreads();
        }
    }

    #pragma unroll
    for (int m = 0; m < 2; m++) {
        int r0 = row0 + rw + m * 16 + g;
        int r1 = r0 + 8;
        #pragma unroll
        for (int n = 0; n < 8; n++) {
            int cb = cw + n * 8 + t4 * 2;
            float b0 = bias[cb], b1 = bias[cb + 1];
            float v00 = acc[m][n][0] + b0, v01 = acc[m][n][1] + b1;
            float v10 = acc[m][n][2] + b0, v11 = acc[m][n][3] + b1;
            if (mat == 0) {
                if (r0 < GN)
                    *(__half2*)&d_xl16[(size_t)r0 * 128 + cb] = __floats2half2_rn(v00, v01);
                if (r1 < GN)
                    *(__half2*)&d_xl16[(size_t)r1 * 128 + cb] = __floats2half2_rn(v10, v11);
            } else {
                if (r0 < GN)
                    *(float2*)&d_xr[(size_t)r0 * 128 + cb] = make_float2(v00, v01);
                if (r1 < GN)
                    *(float2*)&d_xr[(size_t)r1 * 128 + cb] = make_float2(v10, v11);
            }
        }
    }
}

// ---------------- fused GATv2 (two warps per row, fp16 xl) --------------
__device__ __forceinline__ float4 xl_load(const uint2* __restrict__ XL16,
                                          int s, int lane) {
    uint2 v = XL16[(size_t)s * 32 + lane];
    float2 f01 = __half22float2(*(__half2*)&v.x);
    float2 f23 = __half22float2(*(__half2*)&v.y);
    return make_float4(f01.x, f01.y, f23.x, f23.y);
}

__device__ __forceinline__ float edge_logit(const float4& xv, const float4& xrv,
                                            const float4& attv) {
    float v, lg;
    v = xv.x + xrv.x; v = v > 0.f ? v : 0.2f * v; lg = v * attv.x;
    v = xv.y + xrv.y; v = v > 0.f ? v : 0.2f * v; lg = fmaf(v, attv.y, lg);
    v = xv.z + xrv.z; v = v > 0.f ? v : 0.2f * v; lg = fmaf(v, attv.z, lg);
    v = xv.w + xrv.w; v = v > 0.f ? v : 0.2f * v; lg = fmaf(v, attv.w, lg);
    return lg;
}

__device__ __forceinline__ void gat_half(const uint2* XL16, int s0, int s1,
                                         int lane, const float4& xrv,
                                         const float4& attv,
                                         float& mx, float& dn, float4& ac)
{
    mx = -1e30f; dn = 0.f;
    ac = make_float4(0.f, 0.f, 0.f, 0.f);
    int cnt = s1 - s0;

    float4 xv0, xv1, xv2, xv3;
    if (cnt >= 4) {
        xv0 = xl_load(XL16, d_csrsrc[s0],     lane);
        xv1 = xl_load(XL16, d_csrsrc[s0 + 1], lane);
        xv2 = xl_load(XL16, d_csrsrc[s0 + 2], lane);
        xv3 = xl_load(XL16, d_csrsrc[s0 + 3], lane);
    }

    int j = s0;
    for (; j + 3 < s1; j += 4) {
        int p0 = (j + 4 < s1) ? d_csrsrc[j + 4] : 0;
        int p1 = (j + 5 < s1) ? d_csrsrc[j + 5] : 0;
        int p2 = (j + 6 < s1) ? d_csrsrc[j + 6] : 0;
        int p3 = (j + 7 < s1) ? d_csrsrc[j + 7] : 0;
        float4 xn0 = xl_load(XL16, p0, lane);
        float4 xn1 = xl_load(XL16, p1, lane);
        float4 xn2 = xl_load(XL16, p2, lane);
        float4 xn3 = xl_load(XL16, p3, lane);

        float lg0 = edge_logit(xv0, xrv, attv);
        float lg1 = edge_logit(xv1, xrv, attv);
        float lg2 = edge_logit(xv2, xrv, attv);
        float lg3 = edge_logit(xv3, xrv, attv);
        lg0 += __shfl_xor_sync(0xffffffffu, lg0, 4);
        lg1 += __shfl_xor_sync(0xffffffffu, lg1, 4);
        lg2 += __shfl_xor_sync(0xffffffffu, lg2, 4);
        lg3 += __shfl_xor_sync(0xffffffffu, lg3, 4);
        lg0 += __shfl_xor_sync(0xffffffffu, lg0, 2);
        lg1 += __shfl_xor_sync(0xffffffffu, lg1, 2);
        lg2 += __shfl_xor_sync(0xffffffffu, lg2, 2);
        lg3 += __shfl_xor_sync(0xffffffffu, lg3, 2);
        lg0 += __shfl_xor_sync(0xffffffffu, lg0, 1);
        lg1 += __shfl_xor_sync(0xffffffffu, lg1, 1);
        lg2 += __shfl_xor_sync(0xffffffffu, lg2, 1);
        lg3 += __shfl_xor_sync(0xffffffffu, lg3, 1);

        float m = fmaxf(fmaxf(lg0, lg1), fmaxf(lg2, lg3));
        float w0 = __expf(lg0 - m);
        float w1 = __expf(lg1 - m);
        float w2 = __expf(lg2 - m);
        float w3 = __expf(lg3 - m);
        float pd = (w0 + w1) + (w2 + w3);
        float4 pa;
        pa.x = fmaf(w0, xv0.x, w1 * xv1.x) + fmaf(w2, xv2.x, w3 * xv3.x);
        pa.y = fmaf(w0, xv0.y, w1 * xv1.y) + fmaf(w2, xv2.y, w3 * xv3.y);
        pa.z = fmaf(w0, xv0.z, w1 * xv1.z) + fmaf(w2, xv2.z, w3 * xv3.z);
        pa.w = fmaf(w0, xv0.w, w1 * xv1.w) + fmaf(w2, xv2.w, w3 * xv3.w);

        float nm = fmaxf(mx, m);
        float a  = __expf(mx - nm);
        float b  = __expf(m - nm);
        dn = fmaf(dn, a, pd * b);
        ac.x = fmaf(ac.x, a, pa.x * b);
        ac.y = fmaf(ac.y, a, pa.y * b);
        ac.z = fmaf(ac.z, a, pa.z * b);
        ac.w = fmaf(ac.w, a, pa.w * b);
        mx = nm;

        xv0 = xn0; xv1 = xn1; xv2 = xn2; xv3 = xn3;
    }

    for (; j < s1; j++) {
        float4 xv = xl_load(XL16, d_csrsrc[j], lane);
        float lg = edge_logit(xv, xrv, attv);
        lg += __shfl_xor_sync(0xffffffffu, lg, 4);
        lg += __shfl_xor_sync(0xffffffffu, lg, 2);
        lg += __shfl_xor_sync(0xffffffffu, lg, 1);
        float nm = fmaxf(mx, lg);
        float a  = __expf(mx - nm);
        float w  = __expf(lg - nm);
        dn = fmaf(dn, a, w);
        ac.x = fmaf(ac.x, a, w * xv.x);
        ac.y = fmaf(ac.y, a, w * xv.y);
        ac.z = fmaf(ac.z, a, w * xv.z);
        ac.w = fmaf(ac.w, a, w * xv.w);
        mx = nm;
    }
}

__global__ void __launch_bounds__(256) gat_row_kernel(const float* __restrict__ att,
                                                      const float* __restrict__ bias)
{
    __shared__ float s_mx[4][32], s_dn[4][32];
    __shared__ float s_ac[4][4][32];

    int w    = threadIdx.x >> 5;
    int lane = threadIdx.x & 31;
    int ridx = w >> 1;
    int half = w & 1;
    int row  = blockIdx.x * 4 + ridx;
    if (row >= GN) return;

    float4 attv = ((const float4*)att)[lane];
    float4 xrv  = ((const float4*)d_xr)[(size_t)row * 32 + lane];

    int e0 = d_rowstart[row], e1 = d_rowstart[row + 1];
    int mid = e0 + ((e1 - e0 + 1) >> 1);
    int s0 = half ? mid : e0;
    int s1 = half ? e1  : mid;

    const uint2* XL16 = (const uint2*)d_xl16;

    float mx, dn; float4 ac;
    gat_half(XL16, s0, s1, lane, xrv, attv, mx, dn, ac);

    if (half) {
        s_mx[ridx][lane] = mx;
        s_dn[ridx][lane] = dn;
        s_ac[ridx][0][lane] = ac.x;
        s_ac[ridx][1][lane] = ac.y;
        s_ac[ridx][2][lane] = ac.z;
        s_ac[ridx][3][lane] = ac.w;
    }
    __syncthreads();
    if (half) return;

    float mxB = s_mx[ridx][lane];
    float dnB = s_dn[ridx][lane];
    float nm = fmaxf(mx, mxB);
    float a  = __expf(mx - nm);
    float b  = __expf(mxB - nm);
    float dnT = fmaf(dn, a, dnB * b);
    float4 acT;
    acT.x = fmaf(ac.x, a, s_ac[ridx][0][lane] * b);
    acT.y = fmaf(ac.y, a, s_ac[ridx][1][lane] * b);
    acT.z = fmaf(ac.z, a, s_ac[ridx][2][lane] * b);
    acT.w = fmaf(ac.w, a, s_ac[ridx][3][lane] * b);

    float inv = 1.f / dnT;
    float4 bv = ((const float4*)bias)[lane];
    float4 o;
    o.x = fmaxf(fmaf(acT.x, inv, bv.x), 0.f);
    o.y = fmaxf(fmaf(acT.y, inv, bv.y), 0.f);
    o.z = fmaxf(fmaf(acT.z, inv, bv.z), 0.f);
    o.w = fmaxf(fmaf(acT.w, inv, bv.w), 0.f);
    ((float4*)d_h)[(size_t)row * 32 + lane] = o;
}

// ---------------- pooling (count folded into pool) ----------------------
__global__ void pool_kernel(const void* __restrict__ batch) {
    const int CHUNK = 256;
    int n0 = blockIdx.x * CHUNK;
    int n1 = n0 + CHUNK; if (n1 > GN) n1 = GN;
    int col = threadIdx.x;
    int is64 = d_is64;
    int curg = -1;
    float acc = 0.f;
    int run = 0;
    for (int n = n0; n < n1; n++) {
        int g = edge_at(batch, n, is64);
        if (g != curg) {
            if (curg >= 0) {
                atomicAdd(&d_pool[curg * 128 + col], acc);
                if (col == 0) atomicAdd(&d_cnt[curg], (float)run);
            }
            curg = g; acc = 0.f; run = 0;
        }
        acc += d_h[(size_t)n * 128 + col];
        run++;
    }
    if (curg >= 0) {
        atomicAdd(&d_pool[curg * 128 + col], acc);
        if (col == 0) atomicAdd(&d_cnt[curg], (float)run);
    }
}

// ---------------- classifier ----------------
__global__ void classifier_kernel(
    const float* __restrict__ Wc1, const float* __restrict__ bc1,
    const float* __restrict__ Wc2, const float* __restrict__ bc2,
    float* __restrict__ out)
{
    int g = threadIdx.x;
    if (g >= GG) return;
    float inv = 1.f / fmaxf(d_cnt[g], 1.f);
    float z[8];
    #pragma unroll
    for (int j = 0; j < 8; j++) {
        float s = 0.f;
        for (int k = 0; k < 128; k++)
            s += d_pool[g * 128 + k] * Wc1[j * 128 + k];
        s = s * inv + bc1[j];
        z[j] = fmaxf(s, 0.f);
    }
    float o = bc2[0];
    #pragma unroll
    for (int j = 0; j < 8; j++) o += z[j] * Wc2[j];
    out[g] = o;
}

// ---------------- launch ----------------
extern "C" void kernel_launch(void* const* d_in, const int* in_sizes, int n_in,
                              void* d_out, int out_size) {
    const float* x     = (const float*)d_in[0];
    const void*  ei    = d_in[1];
    const void*  batch = d_in[2];
    const float* Wl0 = (const float*)d_in[3];
    const float* bl0 = (const float*)d_in[4];
    const float* Wr0 = (const float*)d_in[5];
    const float* br0 = (const float*)d_in[6];
    const float* at0 = (const float*)d_in[7];
    const float* bi0 = (const float*)d_in[8];
    const float* Wl1 = (const float*)d_in[9];
    const float* bl1 = (const float*)d_in[10];
    const float* Wr1 = (const float*)d_in[11];
    const float* br1 = (const float*)d_in[12];
    const float* at1 = (const float*)d_in[13];
    const float* bi1 = (const float*)d_in[14];
    const float* Wc1 = (const float*)d_in[15];
    const float* bc1 = (const float*)d_in[16];
    const float* Wc2 = (const float*)d_in[17];
    const float* bc2 = (const float*)d_in[18];
    float* out = (float*)d_out;

    g_sh.init();   // no-op if ctor already ran

    const dim3 GEMM_GRID((GN + 127) / 128, 2);

    // Fork: gemm layer-0 runs on the side stream, concurrent with CSR build.
    cudaEventRecord(g_sh.evFork, 0);
    cudaStreamWaitEvent(g_sh.s, g_sh.evFork, 0);
    gemm_kernel<<<GEMM_GRID, 256, 0, g_sh.s>>>(x, Wl0, bl0, Wr0, br0, 0);
    cudaEventRecord(g_sh.evJoin, g_sh.s);

    // CSR build chain on the main (capture) stream.
    init_kernel<<<(GN + 255) / 256, 256>>>((const int*)ei);
    hist_kernel<<<(EP + 255) / 256, 256>>>(ei);
    chunk_sum_kernel<<<NCH, 256>>>();
    tops_kernel<<<1, 128>>>();
    scan_apply_kernel<<<NCH, 512>>>();
    scatter_kernel<<<(EP + 255) / 256, 256>>>(ei);

    // Join: gat_row needs both CSR and gemm layer-0 outputs.
    cudaStreamWaitEvent(0, g_sh.evJoin, 0);

    gat_row_kernel<<<(GN + 3) / 4, 256>>>(at0, bi0);
    gemm_kernel<<<GEMM_GRID, 256>>>(x, Wl1, bl1, Wr1, br1, 1);
    gat_row_kernel<<<(GN + 3) / 4, 256>>>(at1, bi1);

    pool_kernel<<<(GN + 255) / 256, 128>>>(batch);
    classifier_kernel<<<1, 64>>>(Wc1, bc1, Wc2, bc2, out);
}

// round 14
// speedup vs baseline: 1.0904x; 1.0036x over previous
#include <cuda_runtime.h>
#include <cuda_fp16.h>

#define GN 50000
#define GE 800000
#define EP 850000   // GE + GN self-loops
#define GG 64
#define NCH 98      // ceil(GN/512)

// ---------------- scratch (device globals; no allocation) ----------------
__device__ __align__(16) __half d_xl16[GN * 128];
__device__ __align__(16) float  d_xr[GN * 128];
__device__ __align__(16) float  d_h[GN * 128];
__device__ int   d_rowcnt[GN];
__device__ int   d_rowstart[GN + 1];
__device__ int   d_rowfill[GN];
__device__ int   d_csrsrc[EP];
__device__ int   d_chunksum[NCH];
__device__ float d_pool[GG * 128];
__device__ float d_cnt[GG];
__device__ int   d_is64;

__device__ __forceinline__ int edge_at(const void* ei, int idx, int is64) {
    return is64 ? (int)((const long long*)ei)[idx] : ((const int*)ei)[idx];
}

// ---------------- side stream + events (created once, before tracking) ---
struct StreamHolder {
    cudaStream_t s = nullptr;
    cudaEvent_t evFork = nullptr, evJoin = nullptr;
    StreamHolder() { init(); }
    void init() {
        if (!s) {
            cudaStreamCreateWithFlags(&s, cudaStreamNonBlocking);
            cudaEventCreateWithFlags(&evFork, cudaEventDisableTiming);
            cudaEventCreateWithFlags(&evJoin, cudaEventDisableTiming);
        }
    }
};
static StreamHolder g_sh;

// ---------------- fused init: width detect + all zeroing ----------------
__global__ void init_kernel(const int* __restrict__ ei32) {
    int i = blockIdx.x * blockDim.x + threadIdx.x;
    if (i == 0) {
        int any = 0;
        #pragma unroll
        for (int k = 1; k < 128; k += 2) any |= ei32[k];
        d_is64 = (any == 0) ? 1 : 0;
    }
    if (i < GN) d_rowcnt[i] = 0;
    if (i < GG * 128) d_pool[i] = 0.f;
    if (i < GG) d_cnt[i] = 0.f;
}

// ---------------- CSR build: hist -> scan -> scatter ----------------
__global__ void hist_kernel(const void* __restrict__ ei) {
    int i = blockIdx.x * blockDim.x + threadIdx.x;
    if (i >= EP) return;
    int is64 = d_is64;
    int dd = (i < GE) ? edge_at(ei, GE + i, is64) : (i - GE);
    atomicAdd(&d_rowcnt[dd], 1);
}

__global__ void chunk_sum_kernel() {
    __shared__ int sh[256];
    int b = blockIdx.x, t = threadIdx.x;
    int base = b * 512;
    int v = 0;
    int i0 = base + t;       if (i0 < GN) v += d_rowcnt[i0];
    int i1 = base + 256 + t; if (i1 < GN) v += d_rowcnt[i1];
    sh[t] = v; __syncthreads();
    for (int off = 128; off; off >>= 1) {
        if (t < off) sh[t] += sh[t + off];
        __syncthreads();
    }
    if (t == 0) d_chunksum[b] = sh[0];
}

__global__ void tops_kernel() {
    __shared__ int sh[128];
    int t = threadIdx.x;
    int v = (t < NCH) ? d_chunksum[t] : 0;
    sh[t] = v; __syncthreads();
    for (int off = 1; off < 128; off <<= 1) {
        int a = (t >= off) ? sh[t - off] : 0;
        __syncthreads();
        sh[t] += a;
        __syncthreads();
    }
    if (t < NCH) d_chunksum[t] = sh[t] - v;   // exclusive
    if (t == 0) d_rowstart[GN] = EP;
}

__global__ void scan_apply_kernel() {
    __shared__ int sh[512];
    int b = blockIdx.x, t = threadIdx.x;
    int i = b * 512 + t;
    int v = (i < GN) ? d_rowcnt[i] : 0;
    sh[t] = v; __syncthreads();
    for (int off = 1; off < 512; off <<= 1) {
        int a = (t >= off) ? sh[t - off] : 0;
        __syncthreads();
        sh[t] += a;
        __syncthreads();
    }
    if (i < GN) {
        int excl = sh[t] - v + d_chunksum[b];
        d_rowstart[i] = excl;
        d_rowfill[i]  = excl;
    }
}

__global__ void scatter_kernel(const void* __restrict__ ei) {
    int i = blockIdx.x * blockDim.x + threadIdx.x;
    if (i >= EP) return;
    int is64 = d_is64;
    int ss, dd;
    if (i < GE) { ss = edge_at(ei, i, is64); dd = edge_at(ei, GE + i, is64); }
    else        { ss = i - GE; dd = ss; }
    int pos = atomicAdd(&d_rowfill[dd], 1);
    d_csrsrc[pos] = ss;
}

// ---------------- tf32x3 tensor-core GEMM (128x128 tile) ----------------
__device__ __forceinline__ void tf32_split(float x, float& hi, float& lo) {
    unsigned u;
    asm("cvt.rna.tf32.f32 %0, %1;" : "=r"(u) : "f"(x));
    hi = __uint_as_float(u);
    float r = x - hi;
    unsigned v;
    asm("cvt.rna.tf32.f32 %0, %1;" : "=r"(v) : "f"(r));
    lo = __uint_as_float(v);
}

__device__ __forceinline__ void mma_tf32(float* c,
                                         float a0, float a1, float a2, float a3,
                                         float b0, float b1) {
    asm("mma.sync.aligned.m16n8k8.row.col.f32.tf32.tf32.f32 "
        "{%0,%1,%2,%3}, {%4,%5,%6,%7}, {%8,%9}, {%0,%1,%2,%3};"
        : "+f"(c[0]), "+f"(c[1]), "+f"(c[2]), "+f"(c[3])
        : "r"(__float_as_uint(a0)), "r"(__float_as_uint(a1)),
          "r"(__float_as_uint(a2)), "r"(__float_as_uint(a3)),
          "r"(__float_as_uint(b0)), "r"(__float_as_uint(b1)));
}

#define SP 136   // smem pitch (floats)

__global__ void __launch_bounds__(256) gemm_kernel(
    const float* __restrict__ x_in,
    const float* __restrict__ Wl, const float* __restrict__ bl,
    const float* __restrict__ Wr, const float* __restrict__ br,
    int use_h)
{
    const float* A = use_h ? d_h : x_in;
    int mat = blockIdx.y;
    const float* W    = mat ? Wr : Wl;
    const float* bias = mat ? br : bl;
    int row0 = blockIdx.x * 128;

    __shared__ float As_hi[2][8 * SP];
    __shared__ float As_lo[2][8 * SP];
    __shared__ float Bs_hi[2][8 * SP];
    __shared__ float Bs_lo[2][8 * SP];

    int tid  = threadIdx.x;
    int w    = tid >> 5;
    int lane = tid & 31;
    int g    = lane >> 2;
    int t4   = lane & 3;
    int rw   = (w & 3) * 32;
    int cw   = (w >> 2) * 64;

    int lrow = tid >> 1;
    int lq   = tid & 1;

    bool okA = (row0 + lrow) < GN;
    const float* Aptr = A + (size_t)(row0 + lrow) * 128 + lq * 4;
    const float* Wptr = W + (size_t)lrow * 128 + lq * 4;

    float acc[2][8][4];
    #pragma unroll
    for (int m = 0; m < 2; m++)
        #pragma unroll
        for (int n = 0; n < 8; n++)
            #pragma unroll
            for (int q = 0; q < 4; q++) acc[m][n][q] = 0.f;

    {
        float4 av = okA ? *(const float4*)Aptr : make_float4(0.f, 0.f, 0.f, 0.f);
        float4 wv = *(const float4*)Wptr;
        float ah[4], al[4], wh[4], wl[4];
        tf32_split(av.x, ah[0], al[0]); tf32_split(av.y, ah[1], al[1]);
        tf32_split(av.z, ah[2], al[2]); tf32_split(av.w, ah[3], al[3]);
        tf32_split(wv.x, wh[0], wl[0]); tf32_split(wv.y, wh[1], wl[1]);
        tf32_split(wv.z, wh[2], wl[2]); tf32_split(wv.w, wh[3], wl[3]);
        #pragma unroll
        for (int m = 0; m < 4; m++) {
            int k = lq * 4 + m;
            As_hi[0][k * SP + lrow] = ah[m];
            As_lo[0][k * SP + lrow] = al[m];
            Bs_hi[0][k * SP + lrow] = wh[m];
            Bs_lo[0][k * SP + lrow] = wl[m];
        }
    }
    __syncthreads();

    for (int kc = 0; kc < 16; kc++) {
        int p = kc & 1;

        float4 av, wv;
        if (kc < 15) {
            av = okA ? *(const float4*)(Aptr + (kc + 1) * 8)
                     : make_float4(0.f, 0.f, 0.f, 0.f);
            wv = *(const float4*)(Wptr + (kc + 1) * 8);
        }

        float Ah[2][4], Al[2][4];
        #pragma unroll
        for (int m = 0; m < 2; m++) {
            int rb = rw + m * 16;
            Ah[m][0] = As_hi[p][t4 * SP + rb + g];
            Ah[m][1] = As_hi[p][t4 * SP + rb + g + 8];
            Ah[m][2] = As_hi[p][(t4 + 4) * SP + rb + g];
            Ah[m][3] = As_hi[p][(t4 + 4) * SP + rb + g + 8];
            Al[m][0] = As_lo[p][t4 * SP + rb + g];
            Al[m][1] = As_lo[p][t4 * SP + rb + g + 8];
            Al[m][2] = As_lo[p][(t4 + 4) * SP + rb + g];
            Al[m][3] = As_lo[p][(t4 + 4) * SP + rb + g + 8];
        }

        #pragma unroll
        for (int n = 0; n < 8; n++) {
            int cb = cw + n * 8;
            float bh0 = Bs_hi[p][t4 * SP + cb + g];
            float bh1 = Bs_hi[p][(t4 + 4) * SP + cb + g];
            float bl0 = Bs_lo[p][t4 * SP + cb + g];
            float bl1 = Bs_lo[p][(t4 + 4) * SP + cb + g];
            #pragma unroll
            for (int m = 0; m < 2; m++) {
                mma_tf32(acc[m][n], Ah[m][0], Ah[m][1], Ah[m][2], Ah[m][3], bh0, bh1);
                mma_tf32(acc[m][n], Ah[m][0], Ah[m][1], Ah[m][2], Ah[m][3], bl0, bl1);
                mma_tf32(acc[m][n], Al[m][0], Al[m][1], Al[m][2], Al[m][3], bh0, bh1);
            }
        }

        if (kc < 15) {
            float ah[4], al[4], wh[4], wl[4];
            tf32_split(av.x, ah[0], al[0]); tf32_split(av.y, ah[1], al[1]);
            tf32_split(av.z, ah[2], al[2]); tf32_split(av.w, ah[3], al[3]);
            tf32_split(wv.x, wh[0], wl[0]); tf32_split(wv.y, wh[1], wl[1]);
            tf32_split(wv.z, wh[2], wl[2]); tf32_split(wv.w, wh[3], wl[3]);
            int q = 1 - p;
            #pragma unroll
            for (int m = 0; m < 4; m++) {
                int k = lq * 4 + m;
                As_hi[q][k * SP + lrow] = ah[m];
                As_lo[q][k * SP + lrow] = al[m];
                Bs_hi[q][k * SP + lrow] = wh[m];
                Bs_lo[q][k * SP + lrow] = wl[m];
            }
            __syncthreads();
        }
    }

    #pragma unroll
    for (int m = 0; m < 2; m++) {
        int r0 = row0 + rw + m * 16 + g;
        int r1 = r0 + 8;
        #pragma unroll
        for (int n = 0; n < 8; n++) {
            int cb = cw + n * 8 + t4 * 2;
            float b0 = bias[cb], b1 = bias[cb + 1];
            float v00 = acc[m][n][0] + b0, v01 = acc[m][n][1] + b1;
            float v10 = acc[m][n][2] + b0, v11 = acc[m][n][3] + b1;
            if (mat == 0) {
                if (r0 < GN)
                    *(__half2*)&d_xl16[(size_t)r0 * 128 + cb] = __floats2half2_rn(v00, v01);
                if (r1 < GN)
                    *(__half2*)&d_xl16[(size_t)r1 * 128 + cb] = __floats2half2_rn(v10, v11);
            } else {
                if (r0 < GN)
                    *(float2*)&d_xr[(size_t)r0 * 128 + cb] = make_float2(v00, v01);
                if (r1 < GN)
                    *(float2*)&d_xr[(size_t)r1 * 128 + cb] = make_float2(v10, v11);
            }
        }
    }
}

// ---------------- fused GATv2 (two warps/row, register-resident indices) -
__device__ __forceinline__ float4 xl_load(const uint2* __restrict__ XL16,
                                          int s, int lane) {
    uint2 v = XL16[(size_t)s * 32 + lane];
    float2 f01 = __half22float2(*(__half2*)&v.x);
    float2 f23 = __half22float2(*(__half2*)&v.y);
    return make_float4(f01.x, f01.y, f23.x, f23.y);
}

__device__ __forceinline__ float edge_logit(const float4& xv, const float4& xrv,
                                            const float4& attv) {
    float v, lg;
    v = xv.x + xrv.x; v = v > 0.f ? v : 0.2f * v; lg = v * attv.x;
    v = xv.y + xrv.y; v = v > 0.f ? v : 0.2f * v; lg = fmaf(v, attv.y, lg);
    v = xv.z + xrv.z; v = v > 0.f ? v : 0.2f * v; lg = fmaf(v, attv.z, lg);
    v = xv.w + xrv.w; v = v > 0.f ? v : 0.2f * v; lg = fmaf(v, attv.w, lg);
    return lg;
}

// Process CSR range [s0,s1): one coalesced index load per 32 edges, then
// shuffle-broadcast indices (no per-edge index LDG, no 2-level chase).
__device__ __forceinline__ void gat_half(const uint2* XL16, int s0, int s1,
                                         int lane, const float4& xrv,
                                         const float4& attv,
                                         float& mx, float& dn, float4& ac)
{
    mx = -1e30f; dn = 0.f;
    ac = make_float4(0.f, 0.f, 0.f, 0.f);

    for (int base = s0; base < s1; base += 32) {
        int gi = base + lane;
        int idx = (gi < s1) ? d_csrsrc[gi] : 0;
        int n = s1 - base; if (n > 32) n = 32;

        for (int k0 = 0; k0 < n; k0 += 4) {
            int c1 = (k0 + 1) & 31, c2 = (k0 + 2) & 31, c3 = (k0 + 3) & 31;
            int i0 = __shfl_sync(0xffffffffu, idx, k0);
            int i1 = __shfl_sync(0xffffffffu, idx, c1);
            int i2 = __shfl_sync(0xffffffffu, idx, c2);
            int i3 = __shfl_sync(0xffffffffu, idx, c3);
            float4 xv0 = xl_load(XL16, i0, lane);
            float4 xv1 = xl_load(XL16, i1, lane);
            float4 xv2 = xl_load(XL16, i2, lane);
            float4 xv3 = xl_load(XL16, i3, lane);

            float lg0 = edge_logit(xv0, xrv, attv);
            float lg1 = edge_logit(xv1, xrv, attv);
            float lg2 = edge_logit(xv2, xrv, attv);
            float lg3 = edge_logit(xv3, xrv, attv);
            lg0 += __shfl_xor_sync(0xffffffffu, lg0, 4);
            lg1 += __shfl_xor_sync(0xffffffffu, lg1, 4);
            lg2 += __shfl_xor_sync(0xffffffffu, lg2, 4);
            lg3 += __shfl_xor_sync(0xffffffffu, lg3, 4);
            lg0 += __shfl_xor_sync(0xffffffffu, lg0, 2);
            lg1 += __shfl_xor_sync(0xffffffffu, lg1, 2);
            lg2 += __shfl_xor_sync(0xffffffffu, lg2, 2);
            lg3 += __shfl_xor_sync(0xffffffffu, lg3, 2);
            lg0 += __shfl_xor_sync(0xffffffffu, lg0, 1);
            lg1 += __shfl_xor_sync(0xffffffffu, lg1, 1);
            lg2 += __shfl_xor_sync(0xffffffffu, lg2, 1);
            lg3 += __shfl_xor_sync(0xffffffffu, lg3, 1);

            // mask tail edges (weight -> exactly 0)
            if (k0 + 1 >= n) lg1 = -1e30f;
            if (k0 + 2 >= n) lg2 = -1e30f;
            if (k0 + 3 >= n) lg3 = -1e30f;

            float m = fmaxf(fmaxf(lg0, lg1), fmaxf(lg2, lg3));
            float w0 = __expf(lg0 - m);
            float w1 = __expf(lg1 - m);
            float w2 = __expf(lg2 - m);
            float w3 = __expf(lg3 - m);
            float pd = (w0 + w1) + (w2 + w3);
            float4 pa;
            pa.x = fmaf(w0, xv0.x, w1 * xv1.x) + fmaf(w2, xv2.x, w3 * xv3.x);
            pa.y = fmaf(w0, xv0.y, w1 * xv1.y) + fmaf(w2, xv2.y, w3 * xv3.y);
            pa.z = fmaf(w0, xv0.z, w1 * xv1.z) + fmaf(w2, xv2.z, w3 * xv3.z);
            pa.w = fmaf(w0, xv0.w, w1 * xv1.w) + fmaf(w2, xv2.w, w3 * xv3.w);

            float nm = fmaxf(mx, m);
            float a  = __expf(mx - nm);
            float b  = __expf(m - nm);
            dn = fmaf(dn, a, pd * b);
            ac.x = fmaf(ac.x, a, pa.x * b);
            ac.y = fmaf(ac.y, a, pa.y * b);
            ac.z = fmaf(ac.z, a, pa.z * b);
            ac.w = fmaf(ac.w, a, pa.w * b);
            mx = nm;
        }
    }
}

__global__ void __launch_bounds__(256) gat_row_kernel(const float* __restrict__ att,
                                                      const float* __restrict__ bias)
{
    __shared__ float s_mx[4][32], s_dn[4][32];
    __shared__ float s_ac[4][4][32];

    int w    = threadIdx.x >> 5;
    int lane = threadIdx.x & 31;
    int ridx = w >> 1;
    int half = w & 1;
    int row  = blockIdx.x * 4 + ridx;
    if (row >= GN) return;

    float4 attv = ((const float4*)att)[lane];
    float4 xrv  = ((const float4*)d_xr)[(size_t)row * 32 + lane];

    int e0 = d_rowstart[row], e1 = d_rowstart[row + 1];
    int mid = e0 + ((e1 - e0 + 1) >> 1);
    int s0 = half ? mid : e0;
    int s1 = half ? e1  : mid;

    const uint2* XL16 = (const uint2*)d_xl16;

    float mx, dn; float4 ac;
    gat_half(XL16, s0, s1, lane, xrv, attv, mx, dn, ac);

    if (half) {
        s_mx[ridx][lane] = mx;
        s_dn[ridx][lane] = dn;
        s_ac[ridx][0][lane] = ac.x;
        s_ac[ridx][1][lane] = ac.y;
        s_ac[ridx][2][lane] = ac.z;
        s_ac[ridx][3][lane] = ac.w;
    }
    __syncthreads();
    if (half) return;

    float mxB = s_mx[ridx][lane];
    float dnB = s_dn[ridx][lane];
    float nm = fmaxf(mx, mxB);
    float a  = __expf(mx - nm);
    float b  = __expf(mxB - nm);
    float dnT = fmaf(dn, a, dnB * b);
    float4 acT;
    acT.x = fmaf(ac.x, a, s_ac[ridx][0][lane] * b);
    acT.y = fmaf(ac.y, a, s_ac[ridx][1][lane] * b);
    acT.z = fmaf(ac.z, a, s_ac[ridx][2][lane] * b);
    acT.w = fmaf(ac.w, a, s_ac[ridx][3][lane] * b);

    float inv = 1.f / dnT;
    float4 bv = ((const float4*)bias)[lane];
    float4 o;
    o.x = fmaxf(fmaf(acT.x, inv, bv.x), 0.f);
    o.y = fmaxf(fmaf(acT.y, inv, bv.y), 0.f);
    o.z = fmaxf(fmaf(acT.z, inv, bv.z), 0.f);
    o.w = fmaxf(fmaf(acT.w, inv, bv.w), 0.f);
    ((float4*)d_h)[(size_t)row * 32 + lane] = o;
}

// ---------------- pooling (count folded into pool) ----------------------
__global__ void pool_kernel(const void* __restrict__ batch) {
    const int CHUNK = 256;
    int n0 = blockIdx.x * CHUNK;
    int n1 = n0 + CHUNK; if (n1 > GN) n1 = GN;
    int col = threadIdx.x;
    int is64 = d_is64;
    int curg = -1;
    float acc = 0.f;
    int run = 0;
    for (int n = n0; n < n1; n++) {
        int g = edge_at(batch, n, is64);
        if (g != curg) {
            if (curg >= 0) {
                atomicAdd(&d_pool[curg * 128 + col], acc);
                if (col == 0) atomicAdd(&d_cnt[curg], (float)run);
            }
            curg = g; acc = 0.f; run = 0;
        }
        acc += d_h[(size_t)n * 128 + col];
        run++;
    }
    if (curg >= 0) {
        atomicAdd(&d_pool[curg * 128 + col], acc);
        if (col == 0) atomicAdd(&d_cnt[curg], (float)run);
    }
}

// ---------------- classifier ----------------
__global__ void classifier_kernel(
    const float* __restrict__ Wc1, const float* __restrict__ bc1,
    const float* __restrict__ Wc2, const float* __restrict__ bc2,
    float* __restrict__ out)
{
    int g = threadIdx.x;
    if (g >= GG) return;
    float inv = 1.f / fmaxf(d_cnt[g], 1.f);
    float z[8];
    #pragma unroll
    for (int j = 0; j < 8; j++) {
        float s = 0.f;
        for (int k = 0; k < 128; k++)
            s += d_pool[g * 128 + k] * Wc1[j * 128 + k];
        s = s * inv + bc1[j];
        z[j] = fmaxf(s, 0.f);
    }
    float o = bc2[0];
    #pragma unroll
    for (int j = 0; j < 8; j++) o += z[j] * Wc2[j];
    out[g] = o;
}

// ---------------- launch ----------------
extern "C" void kernel_launch(void* const* d_in, const int* in_sizes, int n_in,
                              void* d_out, int out_size) {
    const float* x     = (const float*)d_in[0];
    const void*  ei    = d_in[1];
    const void*  batch = d_in[2];
    const float* Wl0 = (const float*)d_in[3];
    const float* bl0 = (const float*)d_in[4];
    const float* Wr0 = (const float*)d_in[5];
    const float* br0 = (const float*)d_in[6];
    const float* at0 = (const float*)d_in[7];
    const float* bi0 = (const float*)d_in[8];
    const float* Wl1 = (const float*)d_in[9];
    const float* bl1 = (const float*)d_in[10];
    const float* Wr1 = (const float*)d_in[11];
    const float* br1 = (const float*)d_in[12];
    const float* at1 = (const float*)d_in[13];
    const float* bi1 = (const float*)d_in[14];
    const float* Wc1 = (const float*)d_in[15];
    const float* bc1 = (const float*)d_in[16];
    const float* Wc2 = (const float*)d_in[17];
    const float* bc2 = (const float*)d_in[18];
    float* out = (float*)d_out;

    g_sh.init();

    const dim3 GEMM_GRID((GN + 127) / 128, 2);

    // Fork: gemm layer-0 on side stream, concurrent with CSR build.
    cudaEventRecord(g_sh.evFork, 0);
    cudaStreamWaitEvent(g_sh.s, g_sh.evFork, 0);
    gemm_kernel<<<GEMM_GRID, 256, 0, g_sh.s>>>(x, Wl0, bl0, Wr0, br0, 0);
    cudaEventRecord(g_sh.evJoin, g_sh.s);

    // CSR build chain on the main (capture) stream.
    init_kernel<<<(GN + 255) / 256, 256>>>((const int*)ei);
    hist_kernel<<<(EP + 255) / 256, 256>>>(ei);
    chunk_sum_kernel<<<NCH, 256>>>();
    tops_kernel<<<1, 128>>>();
    scan_apply_kernel<<<NCH, 512>>>();
    scatter_kernel<<<(EP + 255) / 256, 256>>>(ei);

    cudaStreamWaitEvent(0, g_sh.evJoin, 0);

    gat_row_kernel<<<(GN + 3) / 4, 256>>>(at0, bi0);
    gemm_kernel<<<GEMM_GRID, 256>>>(x, Wl1, bl1, Wr1, br1, 1);
    gat_row_kernel<<<(GN + 3) / 4, 256>>>(at1, bi1);

    pool_kernel<<<(GN + 255) / 256, 128>>>(batch);
    classifier_kernel<<<1, 64>>>(Wc1, bc1, Wc2, bc2, out);
}

// round 16
// speedup vs baseline: 1.3086x; 1.2001x over previous
#include <cuda_runtime.h>
#include <cuda_fp16.h>

#define GN 50000
#define GE 800000
#define EP 850000   // GE + GN self-loops
#define GG 64
#define NCH 98      // ceil(GN/512)

// ---------------- scratch (device globals; no allocation) ----------------
__device__ __align__(16) __half d_xl16[GN * 128];
__device__ __align__(16) float  d_xr[GN * 128];
__device__ __align__(16) float  d_h[GN * 128];
__device__ int   d_rowcnt[GN];
__device__ int   d_rowstart[GN + 1];
__device__ int   d_rowfill[GN];
__device__ int   d_csrsrc[EP];
__device__ int   d_chunksum[NCH];
__device__ float d_pool[GG * 128];
__device__ float d_cnt[GG];
__device__ int   d_is64;

__device__ __forceinline__ int edge_at(const void* ei, int idx, int is64) {
    return is64 ? (int)((const long long*)ei)[idx] : ((const int*)ei)[idx];
}

// ---------------- side stream + events (created once, before tracking) ---
struct StreamHolder {
    cudaStream_t s = nullptr;
    cudaEvent_t evFork = nullptr, evJoin = nullptr;
    StreamHolder() { init(); }
    void init() {
        if (!s) {
            cudaStreamCreateWithFlags(&s, cudaStreamNonBlocking);
            cudaEventCreateWithFlags(&evFork, cudaEventDisableTiming);
            cudaEventCreateWithFlags(&evJoin, cudaEventDisableTiming);
        }
    }
};
static StreamHolder g_sh;

// ---------------- fused init: width detect + all zeroing ----------------
__global__ void init_kernel(const int* __restrict__ ei32) {
    int i = blockIdx.x * blockDim.x + threadIdx.x;
    if (i == 0) {
        int any = 0;
        #pragma unroll
        for (int k = 1; k < 128; k += 2) any |= ei32[k];
        d_is64 = (any == 0) ? 1 : 0;
    }
    if (i < GN) d_rowcnt[i] = 0;
    if (i < GG * 128) d_pool[i] = 0.f;
    if (i < GG) d_cnt[i] = 0.f;
}

// ---------------- CSR build: hist -> scan -> scatter ----------------
__global__ void hist_kernel(const void* __restrict__ ei) {
    int i = blockIdx.x * blockDim.x + threadIdx.x;
    if (i >= EP) return;
    int is64 = d_is64;
    int dd = (i < GE) ? edge_at(ei, GE + i, is64) : (i - GE);
    atomicAdd(&d_rowcnt[dd], 1);
}

__global__ void chunk_sum_kernel() {
    __shared__ int sh[256];
    int b = blockIdx.x, t = threadIdx.x;
    int base = b * 512;
    int v = 0;
    int i0 = base + t;       if (i0 < GN) v += d_rowcnt[i0];
    int i1 = base + 256 + t; if (i1 < GN) v += d_rowcnt[i1];
    sh[t] = v; __syncthreads();
    for (int off = 128; off; off >>= 1) {
        if (t < off) sh[t] += sh[t + off];
        __syncthreads();
    }
    if (t == 0) d_chunksum[b] = sh[0];
}

__global__ void tops_kernel() {
    __shared__ int sh[128];
    int t = threadIdx.x;
    int v = (t < NCH) ? d_chunksum[t] : 0;
    sh[t] = v; __syncthreads();
    for (int off = 1; off < 128; off <<= 1) {
        int a = (t >= off) ? sh[t - off] : 0;
        __syncthreads();
        sh[t] += a;
        __syncthreads();
    }
    if (t < NCH) d_chunksum[t] = sh[t] - v;   // exclusive
    if (t == 0) d_rowstart[GN] = EP;
}

__global__ void scan_apply_kernel() {
    __shared__ int sh[512];
    int b = blockIdx.x, t = threadIdx.x;
    int i = b * 512 + t;
    int v = (i < GN) ? d_rowcnt[i] : 0;
    sh[t] = v; __syncthreads();
    for (int off = 1; off < 512; off <<= 1) {
        int a = (t >= off) ? sh[t - off] : 0;
        __syncthreads();
        sh[t] += a;
        __syncthreads();
    }
    if (i < GN) {
        int excl = sh[t] - v + d_chunksum[b];
        d_rowstart[i] = excl;
        d_rowfill[i]  = excl;
    }
}

__global__ void scatter_kernel(const void* __restrict__ ei) {
    int i = blockIdx.x * blockDim.x + threadIdx.x;
    if (i >= EP) return;
    int is64 = d_is64;
    int ss, dd;
    if (i < GE) { ss = edge_at(ei, i, is64); dd = edge_at(ei, GE + i, is64); }
    else        { ss = i - GE; dd = ss; }
    int pos = atomicAdd(&d_rowfill[dd], 1);
    d_csrsrc[pos] = ss;
}

// ---------------- tf32x3 tensor-core GEMM (128x128 tile) ----------------
__device__ __forceinline__ void tf32_split(float x, float& hi, float& lo) {
    unsigned u;
    asm("cvt.rna.tf32.f32 %0, %1;" : "=r"(u) : "f"(x));
    hi = __uint_as_float(u);
    float r = x - hi;
    unsigned v;
    asm("cvt.rna.tf32.f32 %0, %1;" : "=r"(v) : "f"(r));
    lo = __uint_as_float(v);
}

__device__ __forceinline__ void mma_tf32(float* c,
                                         float a0, float a1, float a2, float a3,
                                         float b0, float b1) {
    asm("mma.sync.aligned.m16n8k8.row.col.f32.tf32.tf32.f32 "
        "{%0,%1,%2,%3}, {%4,%5,%6,%7}, {%8,%9}, {%0,%1,%2,%3};"
        : "+f"(c[0]), "+f"(c[1]), "+f"(c[2]), "+f"(c[3])
        : "r"(__float_as_uint(a0)), "r"(__float_as_uint(a1)),
          "r"(__float_as_uint(a2)), "r"(__float_as_uint(a3)),
          "r"(__float_as_uint(b0)), "r"(__float_as_uint(b1)));
}

#define SP 136   // smem pitch (floats)

__global__ void __launch_bounds__(256) gemm_kernel(
    const float* __restrict__ x_in,
    const float* __restrict__ Wl, const float* __restrict__ bl,
    const float* __restrict__ Wr, const float* __restrict__ br,
    int use_h)
{
    const float* A = use_h ? d_h : x_in;
    int mat = blockIdx.y;
    const float* W    = mat ? Wr : Wl;
    const float* bias = mat ? br : bl;
    int row0 = blockIdx.x * 128;

    __shared__ float As_hi[2][8 * SP];
    __shared__ float As_lo[2][8 * SP];
    __shared__ float Bs_hi[2][8 * SP];
    __shared__ float Bs_lo[2][8 * SP];

    int tid  = threadIdx.x;
    int w    = tid >> 5;
    int lane = tid & 31;
    int g    = lane >> 2;
    int t4   = lane & 3;
    int rw   = (w & 3) * 32;
    int cw   = (w >> 2) * 64;

    int lrow = tid >> 1;
    int lq   = tid & 1;

    bool okA = (row0 + lrow) < GN;
    const float* Aptr = A + (size_t)(row0 + lrow) * 128 + lq * 4;
    const float* Wptr = W + (size_t)lrow * 128 + lq * 4;

    float acc[2][8][4];
    #pragma unroll
    for (int m = 0; m < 2; m++)
        #pragma unroll
        for (int n = 0; n < 8; n++)
            #pragma unroll
            for (int q = 0; q < 4; q++) acc[m][n][q] = 0.f;

    {
        float4 av = okA ? *(const float4*)Aptr : make_float4(0.f, 0.f, 0.f, 0.f);
        float4 wv = *(const float4*)Wptr;
        float ah[4], al[4], wh[4], wl[4];
        tf32_split(av.x, ah[0], al[0]); tf32_split(av.y, ah[1], al[1]);
        tf32_split(av.z, ah[2], al[2]); tf32_split(av.w, ah[3], al[3]);
        tf32_split(wv.x, wh[0], wl[0]); tf32_split(wv.y, wh[1], wl[1]);
        tf32_split(wv.z, wh[2], wl[2]); tf32_split(wv.w, wh[3], wl[3]);
        #pragma unroll
        for (int m = 0; m < 4; m++) {
            int k = lq * 4 + m;
            As_hi[0][k * SP + lrow] = ah[m];
            As_lo[0][k * SP + lrow] = al[m];
            Bs_hi[0][k * SP + lrow] = wh[m];
            Bs_lo[0][k * SP + lrow] = wl[m];
        }
    }
    __syncthreads();

    for (int kc = 0; kc < 16; kc++) {
        int p = kc & 1;

        float4 av, wv;
        if (kc < 15) {
            av = okA ? *(const float4*)(Aptr + (kc + 1) * 8)
                     : make_float4(0.f, 0.f, 0.f, 0.f);
            wv = *(const float4*)(Wptr + (kc + 1) * 8);
        }

        float Ah[2][4], Al[2][4];
        #pragma unroll
        for (int m = 0; m < 2; m++) {
            int rb = rw + m * 16;
            Ah[m][0] = As_hi[p][t4 * SP + rb + g];
            Ah[m][1] = As_hi[p][t4 * SP + rb + g + 8];
            Ah[m][2] = As_hi[p][(t4 + 4) * SP + rb + g];
            Ah[m][3] = As_hi[p][(t4 + 4) * SP + rb + g + 8];
            Al[m][0] = As_lo[p][t4 * SP + rb + g];
            Al[m][1] = As_lo[p][t4 * SP + rb + g + 8];
            Al[m][2] = As_lo[p][(t4 + 4) * SP + rb + g];
            Al[m][3] = As_lo[p][(t4 + 4) * SP + rb + g + 8];
        }

        #pragma unroll
        for (int n = 0; n < 8; n++) {
            int cb = cw + n * 8;
            float bh0 = Bs_hi[p][t4 * SP + cb + g];
            float bh1 = Bs_hi[p][(t4 + 4) * SP + cb + g];
            float bl0 = Bs_lo[p][t4 * SP + cb + g];
            float bl1 = Bs_lo[p][(t4 + 4) * SP + cb + g];
            #pragma unroll
            for (int m = 0; m < 2; m++) {
                mma_tf32(acc[m][n], Ah[m][0], Ah[m][1], Ah[m][2], Ah[m][3], bh0, bh1);
                mma_tf32(acc[m][n], Ah[m][0], Ah[m][1], Ah[m][2], Ah[m][3], bl0, bl1);
                mma_tf32(acc[m][n], Al[m][0], Al[m][1], Al[m][2], Al[m][3], bh0, bh1);
            }
        }

        if (kc < 15) {
            float ah[4], al[4], wh[4], wl[4];
            tf32_split(av.x, ah[0], al[0]); tf32_split(av.y, ah[1], al[1]);
            tf32_split(av.z, ah[2], al[2]); tf32_split(av.w, ah[3], al[3]);
            tf32_split(wv.x, wh[0], wl[0]); tf32_split(wv.y, wh[1], wl[1]);
            tf32_split(wv.z, wh[2], wl[2]); tf32_split(wv.w, wh[3], wl[3]);
            int q = 1 - p;
            #pragma unroll
            for (int m = 0; m < 4; m++) {
                int k = lq * 4 + m;
                As_hi[q][k * SP + lrow] = ah[m];
                As_lo[q][k * SP + lrow] = al[m];
                Bs_hi[q][k * SP + lrow] = wh[m];
                Bs_lo[q][k * SP + lrow] = wl[m];
            }
            __syncthreads();
        }
    }

    #pragma unroll
    for (int m = 0; m < 2; m++) {
        int r0 = row0 + rw + m * 16 + g;
        int r1 = r0 + 8;
        #pragma unroll
        for (int n = 0; n < 8; n++) {
            int cb = cw + n * 8 + t4 * 2;
            float b0 = bias[cb], b1 = bias[cb + 1];
            float v00 = acc[m][n][0] + b0, v01 = acc[m][n][1] + b1;
            float v10 = acc[m][n][2] + b0, v11 = acc[m][n][3] + b1;
            if (mat == 0) {
                if (r0 < GN)
                    *(__half2*)&d_xl16[(size_t)r0 * 128 + cb] = __floats2half2_rn(v00, v01);
                if (r1 < GN)
                    *(__half2*)&d_xl16[(size_t)r1 * 128 + cb] = __floats2half2_rn(v10, v11);
            } else {
                if (r0 < GN)
                    *(float2*)&d_xr[(size_t)r0 * 128 + cb] = make_float2(v00, v01);
                if (r1 < GN)
                    *(float2*)&d_xr[(size_t)r1 * 128 + cb] = make_float2(v10, v11);
            }
        }
    }
}

// ---------------- fused GATv2 (two warps/row, register-resident indices) -
__device__ __forceinline__ float4 xl_load(const uint2* __restrict__ XL16,
                                          int s, int lane) {
    uint2 v = XL16[(size_t)s * 32 + lane];
    float2 f01 = __half22float2(*(__half2*)&v.x);
    float2 f23 = __half22float2(*(__half2*)&v.y);
    return make_float4(f01.x, f01.y, f23.x, f23.y);
}

__device__ __forceinline__ float edge_logit(const float4& xv, const float4& xrv,
                                            const float4& attv) {
    float v, lg;
    v = xv.x + xrv.x; v = v > 0.f ? v : 0.2f * v; lg = v * attv.x;
    v = xv.y + xrv.y; v = v > 0.f ? v : 0.2f * v; lg = fmaf(v, attv.y, lg);
    v = xv.z + xrv.z; v = v > 0.f ? v : 0.2f * v; lg = fmaf(v, attv.z, lg);
    v = xv.w + xrv.w; v = v > 0.f ? v : 0.2f * v; lg = fmaf(v, attv.w, lg);
    return lg;
}

__device__ __forceinline__ void gat_half(const uint2* XL16, int s0, int s1,
                                         int lane, const float4& xrv,
                                         const float4& attv,
                                         float& mx, float& dn, float4& ac)
{
    mx = -1e30f; dn = 0.f;
    ac = make_float4(0.f, 0.f, 0.f, 0.f);

    for (int base = s0; base < s1; base += 32) {
        int gi = base + lane;
        int idx = (gi < s1) ? d_csrsrc[gi] : 0;
        int n = s1 - base; if (n > 32) n = 32;

        for (int k0 = 0; k0 < n; k0 += 4) {
            int c1 = (k0 + 1) & 31, c2 = (k0 + 2) & 31, c3 = (k0 + 3) & 31;
            int i0 = __shfl_sync(0xffffffffu, idx, k0);
            int i1 = __shfl_sync(0xffffffffu, idx, c1);
            int i2 = __shfl_sync(0xffffffffu, idx, c2);
            int i3 = __shfl_sync(0xffffffffu, idx, c3);
            float4 xv0 = xl_load(XL16, i0, lane);
            float4 xv1 = xl_load(XL16, i1, lane);
            float4 xv2 = xl_load(XL16, i2, lane);
            float4 xv3 = xl_load(XL16, i3, lane);

            float lg0 = edge_logit(xv0, xrv, attv);
            float lg1 = edge_logit(xv1, xrv, attv);
            float lg2 = edge_logit(xv2, xrv, attv);
            float lg3 = edge_logit(xv3, xrv, attv);
            lg0 += __shfl_xor_sync(0xffffffffu, lg0, 4);
            lg1 += __shfl_xor_sync(0xffffffffu, lg1, 4);
            lg2 += __shfl_xor_sync(0xffffffffu, lg2, 4);
            lg3 += __shfl_xor_sync(0xffffffffu, lg3, 4);
            lg0 += __shfl_xor_sync(0xffffffffu, lg0, 2);
            lg1 += __shfl_xor_sync(0xffffffffu, lg1, 2);
            lg2 += __shfl_xor_sync(0xffffffffu, lg2, 2);
            lg3 += __shfl_xor_sync(0xffffffffu, lg3, 2);
            lg0 += __shfl_xor_sync(0xffffffffu, lg0, 1);
            lg1 += __shfl_xor_sync(0xffffffffu, lg1, 1);
            lg2 += __shfl_xor_sync(0xffffffffu, lg2, 1);
            lg3 += __shfl_xor_sync(0xffffffffu, lg3, 1);

            if (k0 + 1 >= n) lg1 = -1e30f;
            if (k0 + 2 >= n) lg2 = -1e30f;
            if (k0 + 3 >= n) lg3 = -1e30f;

            float m = fmaxf(fmaxf(lg0, lg1), fmaxf(lg2, lg3));
            float w0 = __expf(lg0 - m);
            float w1 = __expf(lg1 - m);
            float w2 = __expf(lg2 - m);
            float w3 = __expf(lg3 - m);
            float pd = (w0 + w1) + (w2 + w3);
            float4 pa;
            pa.x = fmaf(w0, xv0.x, w1 * xv1.x) + fmaf(w2, xv2.x, w3 * xv3.x);
            pa.y = fmaf(w0, xv0.y, w1 * xv1.y) + fmaf(w2, xv2.y, w3 * xv3.y);
            pa.z = fmaf(w0, xv0.z, w1 * xv1.z) + fmaf(w2, xv2.z, w3 * xv3.z);
            pa.w = fmaf(w0, xv0.w, w1 * xv1.w) + fmaf(w2, xv2.w, w3 * xv3.w);

            float nm = fmaxf(mx, m);
            float a  = __expf(mx - nm);
            float b  = __expf(m - nm);
            dn = fmaf(dn, a, pd * b);
            ac.x = fmaf(ac.x, a, pa.x * b);
            ac.y = fmaf(ac.y, a, pa.y * b);
            ac.z = fmaf(ac.z, a, pa.z * b);
            ac.w = fmaf(ac.w, a, pa.w * b);
            mx = nm;
        }
    }
}

__global__ void __launch_bounds__(256) gat_row_kernel(const float* __restrict__ att,
                                                      const float* __restrict__ bias)
{
    __shared__ float s_mx[4][32], s_dn[4][32];
    __shared__ float s_ac[4][4][32];

    int w    = threadIdx.x >> 5;
    int lane = threadIdx.x & 31;
    int ridx = w >> 1;
    int half = w & 1;
    int row  = blockIdx.x * 4 + ridx;
    if (row >= GN) return;

    float4 attv = ((const float4*)att)[lane];
    float4 xrv  = ((const float4*)d_xr)[(size_t)row * 32 + lane];

    int e0 = d_rowstart[row], e1 = d_rowstart[row + 1];
    int mid = e0 + ((e1 - e0 + 1) >> 1);
    int s0 = half ? mid : e0;
    int s1 = half ? e1  : mid;

    const uint2* XL16 = (const uint2*)d_xl16;

    float mx, dn; float4 ac;
    gat_half(XL16, s0, s1, lane, xrv, attv, mx, dn, ac);

    if (half) {
        s_mx[ridx][lane] = mx;
        s_dn[ridx][lane] = dn;
        s_ac[ridx][0][lane] = ac.x;
        s_ac[ridx][1][lane] = ac.y;
        s_ac[ridx][2][lane] = ac.z;
        s_ac[ridx][3][lane] = ac.w;
    }
    __syncthreads();
    if (half) return;

    float mxB = s_mx[ridx][lane];
    float dnB = s_dn[ridx][lane];
    float nm = fmaxf(mx, mxB);
    float a  = __expf(mx - nm);
    float b  = __expf(mxB - nm);
    float dnT = fmaf(dn, a, dnB * b);
    float4 acT;
    acT.x = fmaf(ac.x, a, s_ac[ridx][0][lane] * b);
    acT.y = fmaf(ac.y, a, s_ac[ridx][1][lane] * b);
    acT.z = fmaf(ac.z, a, s_ac[ridx][2][lane] * b);
    acT.w = fmaf(ac.w, a, s_ac[ridx][3][lane] * b);

    float inv = 1.f / dnT;
    float4 bv = ((const float4*)bias)[lane];
    float4 o;
    o.x = fmaxf(fmaf(acT.x, inv, bv.x), 0.f);
    o.y = fmaxf(fmaf(acT.y, inv, bv.y), 0.f);
    o.z = fmaxf(fmaf(acT.z, inv, bv.z), 0.f);
    o.w = fmaxf(fmaf(acT.w, inv, bv.w), 0.f);
    ((float4*)d_h)[(size_t)row * 32 + lane] = o;
}

// ---------------- pooling (parallel + load-batched) ---------------------
#define PCHUNK 64
__global__ void pool_kernel(const void* __restrict__ batch) {
    int n0 = blockIdx.x * PCHUNK;
    int n1 = n0 + PCHUNK; if (n1 > GN) n1 = GN;
    int col = threadIdx.x;
    int is64 = d_is64;
    int curg = -1;
    float acc = 0.f;
    int run = 0;
    for (int n = n0; n < n1; n += 4) {
        int m = n1 - n; if (m > 4) m = 4;
        int   gid[4];
        float hv[4];
        #pragma unroll
        for (int k = 0; k < 4; k++) {
            if (k < m) {
                gid[k] = edge_at(batch, n + k, is64);
                hv[k]  = d_h[(size_t)(n + k) * 128 + col];
            }
        }
        #pragma unroll
        for (int k = 0; k < 4; k++) {
            if (k < m) {
                if (gid[k] != curg) {
                    if (curg >= 0) {
                        atomicAdd(&d_pool[curg * 128 + col], acc);
                        if (col == 0) atomicAdd(&d_cnt[curg], (float)run);
                    }
                    curg = gid[k]; acc = 0.f; run = 0;
                }
                acc += hv[k];
                run++;
            }
        }
    }
    if (curg >= 0) {
        atomicAdd(&d_pool[curg * 128 + col], acc);
        if (col == 0) atomicAdd(&d_cnt[curg], (float)run);
    }
}

// ---------------- classifier ----------------
__global__ void classifier_kernel(
    const float* __restrict__ Wc1, const float* __restrict__ bc1,
    const float* __restrict__ Wc2, const float* __restrict__ bc2,
    float* __restrict__ out)
{
    int g = threadIdx.x;
    if (g >= GG) return;
    float inv = 1.f / fmaxf(d_cnt[g], 1.f);
    float z[8];
    #pragma unroll
    for (int j = 0; j < 8; j++) {
        float s = 0.f;
        for (int k = 0; k < 128; k++)
            s += d_pool[g * 128 + k] * Wc1[j * 128 + k];
        s = s * inv + bc1[j];
        z[j] = fmaxf(s, 0.f);
    }
    float o = bc2[0];
    #pragma unroll
    for (int j = 0; j < 8; j++) o += z[j] * Wc2[j];
    out[g] = o;
}

// ---------------- launch ----------------
extern "C" void kernel_launch(void* const* d_in, const int* in_sizes, int n_in,
                              void* d_out, int out_size) {
    const float* x     = (const float*)d_in[0];
    const void*  ei    = d_in[1];
    const void*  batch = d_in[2];
    const float* Wl0 = (const float*)d_in[3];
    const float* bl0 = (const float*)d_in[4];
    const float* Wr0 = (const float*)d_in[5];
    const float* br0 = (const float*)d_in[6];
    const float* at0 = (const float*)d_in[7];
    const float* bi0 = (const float*)d_in[8];
    const float* Wl1 = (const float*)d_in[9];
    const float* bl1 = (const float*)d_in[10];
    const float* Wr1 = (const float*)d_in[11];
    const float* br1 = (const float*)d_in[12];
    const float* at1 = (const float*)d_in[13];
    const float* bi1 = (const float*)d_in[14];
    const float* Wc1 = (const float*)d_in[15];
    const float* bc1 = (const float*)d_in[16];
    const float* Wc2 = (const float*)d_in[17];
    const float* bc2 = (const float*)d_in[18];
    float* out = (float*)d_out;

    g_sh.init();

    const dim3 GEMM_GRID((GN + 127) / 128, 2);

    // Fork: gemm layer-0 on side stream, concurrent with CSR build.
    cudaEventRecord(g_sh.evFork, 0);
    cudaStreamWaitEvent(g_sh.s, g_sh.evFork, 0);
    gemm_kernel<<<GEMM_GRID, 256, 0, g_sh.s>>>(x, Wl0, bl0, Wr0, br0, 0);
    cudaEventRecord(g_sh.evJoin, g_sh.s);

    // CSR build chain on the main (capture) stream.
    init_kernel<<<(GN + 255) / 256, 256>>>((const int*)ei);
    hist_kernel<<<(EP + 255) / 256, 256>>>(ei);
    chunk_sum_kernel<<<NCH, 256>>>();
    tops_kernel<<<1, 128>>>();
    scan_apply_kernel<<<NCH, 512>>>();
    scatter_kernel<<<(EP + 255) / 256, 256>>>(ei);

    cudaStreamWaitEvent(0, g_sh.evJoin, 0);

    gat_row_kernel<<<(GN + 3) / 4, 256>>>(at0, bi0);
    gemm_kernel<<<GEMM_GRID, 256>>>(x, Wl1, bl1, Wr1, br1, 1);
    gat_row_kernel<<<(GN + 3) / 4, 256>>>(at1, bi1);

    pool_kernel<<<(GN + PCHUNK - 1) / PCHUNK, 128>>>(batch);
    classifier_kernel<<<1, 64>>>(Wc1, bc1, Wc2, bc2, out);
}

// round 17
// speedup vs baseline: 1.4349x; 1.0965x over previous
#include <cuda_runtime.h>
#include <cuda_fp16.h>

#define GN 50000
#define GE 800000
#define EP 850000   // GE + GN self-loops
#define GG 64
#define NCH 98      // ceil(GN/512)

// ---------------- scratch (device globals; no allocation) ----------------
__device__ __align__(16) __half d_xl16[GN * 128];
__device__ __align__(16) float  d_xr[GN * 128];
__device__ __align__(16) float  d_h[GN * 128];
__device__ int   d_rowcnt[GN];
__device__ int   d_rowstart[GN + 1];
__device__ int   d_rowfill[GN];
__device__ int   d_csrsrc[EP];
__device__ int   d_chunksum[NCH];
__device__ float d_pool[GG * 128];
__device__ float d_cnt[GG];
__device__ int   d_is64;

__device__ __forceinline__ int edge_at(const void* ei, int idx, int is64) {
    return is64 ? (int)((const long long*)ei)[idx] : ((const int*)ei)[idx];
}

// ---------------- side stream + events (created once, before tracking) ---
struct StreamHolder {
    cudaStream_t s = nullptr;
    cudaEvent_t evFork = nullptr, evJoin = nullptr;
    StreamHolder() { init(); }
    void init() {
        if (!s) {
            cudaStreamCreateWithFlags(&s, cudaStreamNonBlocking);
            cudaEventCreateWithFlags(&evFork, cudaEventDisableTiming);
            cudaEventCreateWithFlags(&evJoin, cudaEventDisableTiming);
        }
    }
};
static StreamHolder g_sh;

// ---------------- fused init: width detect + all zeroing ----------------
__global__ void init_kernel(const int* __restrict__ ei32) {
    int i = blockIdx.x * blockDim.x + threadIdx.x;
    if (i == 0) {
        int any = 0;
        #pragma unroll
        for (int k = 1; k < 128; k += 2) any |= ei32[k];
        d_is64 = (any == 0) ? 1 : 0;
    }
    if (i < GN) d_rowcnt[i] = 0;
    if (i < GG * 128) d_pool[i] = 0.f;
    if (i < GG) d_cnt[i] = 0.f;
}

// ---------------- CSR build: hist -> scan -> scatter ----------------
__global__ void hist_kernel(const void* __restrict__ ei) {
    int i = blockIdx.x * blockDim.x + threadIdx.x;
    if (i >= EP) return;
    int is64 = d_is64;
    int dd = (i < GE) ? edge_at(ei, GE + i, is64) : (i - GE);
    atomicAdd(&d_rowcnt[dd], 1);
}

__global__ void chunk_sum_kernel() {
    __shared__ int sh[256];
    int b = blockIdx.x, t = threadIdx.x;
    int base = b * 512;
    int v = 0;
    int i0 = base + t;       if (i0 < GN) v += d_rowcnt[i0];
    int i1 = base + 256 + t; if (i1 < GN) v += d_rowcnt[i1];
    sh[t] = v; __syncthreads();
    for (int off = 128; off; off >>= 1) {
        if (t < off) sh[t] += sh[t + off];
        __syncthreads();
    }
    if (t == 0) d_chunksum[b] = sh[0];
}

__global__ void tops_kernel() {
    __shared__ int sh[128];
    int t = threadIdx.x;
    int v = (t < NCH) ? d_chunksum[t] : 0;
    sh[t] = v; __syncthreads();
    for (int off = 1; off < 128; off <<= 1) {
        int a = (t >= off) ? sh[t - off] : 0;
        __syncthreads();
        sh[t] += a;
        __syncthreads();
    }
    if (t < NCH) d_chunksum[t] = sh[t] - v;   // exclusive
    if (t == 0) d_rowstart[GN] = EP;
}

__global__ void scan_apply_kernel() {
    __shared__ int sh[512];
    int b = blockIdx.x, t = threadIdx.x;
    int i = b * 512 + t;
    int v = (i < GN) ? d_rowcnt[i] : 0;
    sh[t] = v; __syncthreads();
    for (int off = 1; off < 512; off <<= 1) {
        int a = (t >= off) ? sh[t - off] : 0;
        __syncthreads();
        sh[t] += a;
        __syncthreads();
    }
    if (i < GN) {
        int excl = sh[t] - v + d_chunksum[b];
        d_rowstart[i] = excl;
        d_rowfill[i]  = excl;
    }
}

__global__ void scatter_kernel(const void* __restrict__ ei) {
    int i = blockIdx.x * blockDim.x + threadIdx.x;
    if (i >= EP) return;
    int is64 = d_is64;
    int ss, dd;
    if (i < GE) { ss = edge_at(ei, i, is64); dd = edge_at(ei, GE + i, is64); }
    else        { ss = i - GE; dd = ss; }
    int pos = atomicAdd(&d_rowfill[dd], 1);
    d_csrsrc[pos] = ss;
}

// ---------------- tf32x2 tensor-core GEMM (128x128 tile) ----------------
// D = Ah*Bh + Ah*Bl (B residual compensated; A residual ~2^-11 ignored).
__device__ __forceinline__ float tf32_rn(float x) {
    unsigned u;
    asm("cvt.rna.tf32.f32 %0, %1;" : "=r"(u) : "f"(x));
    return __uint_as_float(u);
}

__device__ __forceinline__ void tf32_split(float x, float& hi, float& lo) {
    hi = tf32_rn(x);
    lo = tf32_rn(x - hi);
}

__device__ __forceinline__ void mma_tf32(float* c,
                                         float a0, float a1, float a2, float a3,
                                         float b0, float b1) {
    asm("mma.sync.aligned.m16n8k8.row.col.f32.tf32.tf32.f32 "
        "{%0,%1,%2,%3}, {%4,%5,%6,%7}, {%8,%9}, {%0,%1,%2,%3};"
        : "+f"(c[0]), "+f"(c[1]), "+f"(c[2]), "+f"(c[3])
        : "r"(__float_as_uint(a0)), "r"(__float_as_uint(a1)),
          "r"(__float_as_uint(a2)), "r"(__float_as_uint(a3)),
          "r"(__float_as_uint(b0)), "r"(__float_as_uint(b1)));
}

#define SP 136   // smem pitch (floats)

__global__ void __launch_bounds__(256) gemm_kernel(
    const float* __restrict__ x_in,
    const float* __restrict__ Wl, const float* __restrict__ bl,
    const float* __restrict__ Wr, const float* __restrict__ br,
    int use_h)
{
    const float* A = use_h ? d_h : x_in;
    int mat = blockIdx.y;
    const float* W    = mat ? Wr : Wl;
    const float* bias = mat ? br : bl;
    int row0 = blockIdx.x * 128;

    __shared__ float As_hi[2][8 * SP];
    __shared__ float Bs_hi[2][8 * SP];
    __shared__ float Bs_lo[2][8 * SP];

    int tid  = threadIdx.x;
    int w    = tid >> 5;
    int lane = tid & 31;
    int g    = lane >> 2;
    int t4   = lane & 3;
    int rw   = (w & 3) * 32;
    int cw   = (w >> 2) * 64;

    int lrow = tid >> 1;
    int lq   = tid & 1;

    bool okA = (row0 + lrow) < GN;
    const float* Aptr = A + (size_t)(row0 + lrow) * 128 + lq * 4;
    const float* Wptr = W + (size_t)lrow * 128 + lq * 4;

    float acc[2][8][4];
    #pragma unroll
    for (int m = 0; m < 2; m++)
        #pragma unroll
        for (int n = 0; n < 8; n++)
            #pragma unroll
            for (int q = 0; q < 4; q++) acc[m][n][q] = 0.f;

    {
        float4 av = okA ? *(const float4*)Aptr : make_float4(0.f, 0.f, 0.f, 0.f);
        float4 wv = *(const float4*)Wptr;
        float wh[4], wl[4];
        tf32_split(wv.x, wh[0], wl[0]); tf32_split(wv.y, wh[1], wl[1]);
        tf32_split(wv.z, wh[2], wl[2]); tf32_split(wv.w, wh[3], wl[3]);
        float ah[4] = { tf32_rn(av.x), tf32_rn(av.y), tf32_rn(av.z), tf32_rn(av.w) };
        #pragma unroll
        for (int m = 0; m < 4; m++) {
            int k = lq * 4 + m;
            As_hi[0][k * SP + lrow] = ah[m];
            Bs_hi[0][k * SP + lrow] = wh[m];
            Bs_lo[0][k * SP + lrow] = wl[m];
        }
    }
    __syncthreads();

    for (int kc = 0; kc < 16; kc++) {
        int p = kc & 1;

        float4 av, wv;
        if (kc < 15) {
            av = okA ? *(const float4*)(Aptr + (kc + 1) * 8)
                     : make_float4(0.f, 0.f, 0.f, 0.f);
            wv = *(const float4*)(Wptr + (kc + 1) * 8);
        }

        float Ah[2][4];
        #pragma unroll
        for (int m = 0; m < 2; m++) {
            int rb = rw + m * 16;
            Ah[m][0] = As_hi[p][t4 * SP + rb + g];
            Ah[m][1] = As_hi[p][t4 * SP + rb + g + 8];
            Ah[m][2] = As_hi[p][(t4 + 4) * SP + rb + g];
            Ah[m][3] = As_hi[p][(t4 + 4) * SP + rb + g + 8];
        }

        #pragma unroll
        for (int n = 0; n < 8; n++) {
            int cb = cw + n * 8;
            float bh0 = Bs_hi[p][t4 * SP + cb + g];
            float bh1 = Bs_hi[p][(t4 + 4) * SP + cb + g];
            float bl0 = Bs_lo[p][t4 * SP + cb + g];
            float bl1 = Bs_lo[p][(t4 + 4) * SP + cb + g];
            #pragma unroll
            for (int m = 0; m < 2; m++) {
                mma_tf32(acc[m][n], Ah[m][0], Ah[m][1], Ah[m][2], Ah[m][3], bh0, bh1);
                mma_tf32(acc[m][n], Ah[m][0], Ah[m][1], Ah[m][2], Ah[m][3], bl0, bl1);
            }
        }

        if (kc < 15) {
            float wh[4], wl[4];
            tf32_split(wv.x, wh[0], wl[0]); tf32_split(wv.y, wh[1], wl[1]);
            tf32_split(wv.z, wh[2], wl[2]); tf32_split(wv.w, wh[3], wl[3]);
            float ah[4] = { tf32_rn(av.x), tf32_rn(av.y), tf32_rn(av.z), tf32_rn(av.w) };
            int q = 1 - p;
            #pragma unroll
            for (int m = 0; m < 4; m++) {
                int k = lq * 4 + m;
                As_hi[q][k * SP + lrow] = ah[m];
                Bs_hi[q][k * SP + lrow] = wh[m];
                Bs_lo[q][k * SP + lrow] = wl[m];
            }
            __syncthreads();
        }
    }

    #pragma unroll
    for (int m = 0; m < 2; m++) {
        int r0 = row0 + rw + m * 16 + g;
        int r1 = r0 + 8;
        #pragma unroll
        for (int n = 0; n < 8; n++) {
            int cb = cw + n * 8 + t4 * 2;
            float b0 = bias[cb], b1 = bias[cb + 1];
            float v00 = acc[m][n][0] + b0, v01 = acc[m][n][1] + b1;
            float v10 = acc[m][n][2] + b0, v11 = acc[m][n][3] + b1;
            if (mat == 0) {
                if (r0 < GN)
                    *(__half2*)&d_xl16[(size_t)r0 * 128 + cb] = __floats2half2_rn(v00, v01);
                if (r1 < GN)
                    *(__half2*)&d_xl16[(size_t)r1 * 128 + cb] = __floats2half2_rn(v10, v11);
            } else {
                if (r0 < GN)
                    *(float2*)&d_xr[(size_t)r0 * 128 + cb] = make_float2(v00, v01);
                if (r1 < GN)
                    *(float2*)&d_xr[(size_t)r1 * 128 + cb] = make_float2(v10, v11);
            }
        }
    }
}

// ---------------- fused GATv2 (two warps/row, register-resident indices) -
__device__ __forceinline__ float4 xl_load(const uint2* __restrict__ XL16,
                                          int s, int lane) {
    uint2 v = XL16[(size_t)s * 32 + lane];
    float2 f01 = __half22float2(*(__half2*)&v.x);
    float2 f23 = __half22float2(*(__half2*)&v.y);
    return make_float4(f01.x, f01.y, f23.x, f23.y);
}

__device__ __forceinline__ float edge_logit(const float4& xv, const float4& xrv,
                                            const float4& attv) {
    float v, lg;
    v = xv.x + xrv.x; v = v > 0.f ? v : 0.2f * v; lg = v * attv.x;
    v = xv.y + xrv.y; v = v > 0.f ? v : 0.2f * v; lg = fmaf(v, attv.y, lg);
    v = xv.z + xrv.z; v = v > 0.f ? v : 0.2f * v; lg = fmaf(v, attv.z, lg);
    v = xv.w + xrv.w; v = v > 0.f ? v : 0.2f * v; lg = fmaf(v, attv.w, lg);
    return lg;
}

__device__ __forceinline__ void gat_half(const uint2* XL16, int s0, int s1,
                                         int lane, const float4& xrv,
                                         const float4& attv,
                                         float& mx, float& dn, float4& ac)
{
    mx = -1e30f; dn = 0.f;
    ac = make_float4(0.f, 0.f, 0.f, 0.f);

    for (int base = s0; base < s1; base += 32) {
        int gi = base + lane;
        int idx = (gi < s1) ? d_csrsrc[gi] : 0;
        int n = s1 - base; if (n > 32) n = 32;

        for (int k0 = 0; k0 < n; k0 += 4) {
            int c1 = (k0 + 1) & 31, c2 = (k0 + 2) & 31, c3 = (k0 + 3) & 31;
            int i0 = __shfl_sync(0xffffffffu, idx, k0);
            int i1 = __shfl_sync(0xffffffffu, idx, c1);
            int i2 = __shfl_sync(0xffffffffu, idx, c2);
            int i3 = __shfl_sync(0xffffffffu, idx, c3);
            float4 xv0 = xl_load(XL16, i0, lane);
            float4 xv1 = xl_load(XL16, i1, lane);
            float4 xv2 = xl_load(XL16, i2, lane);
            float4 xv3 = xl_load(XL16, i3, lane);

            float lg0 = edge_logit(xv0, xrv, attv);
            float lg1 = edge_logit(xv1, xrv, attv);
            float lg2 = edge_logit(xv2, xrv, attv);
            float lg3 = edge_logit(xv3, xrv, attv);
            lg0 += __shfl_xor_sync(0xffffffffu, lg0, 4);
            lg1 += __shfl_xor_sync(0xffffffffu, lg1, 4);
            lg2 += __shfl_xor_sync(0xffffffffu, lg2, 4);
            lg3 += __shfl_xor_sync(0xffffffffu, lg3, 4);
            lg0 += __shfl_xor_sync(0xffffffffu, lg0, 2);
            lg1 += __shfl_xor_sync(0xffffffffu, lg1, 2);
            lg2 += __shfl_xor_sync(0xffffffffu, lg2, 2);
            lg3 += __shfl_xor_sync(0xffffffffu, lg3, 2);
            lg0 += __shfl_xor_sync(0xffffffffu, lg0, 1);
            lg1 += __shfl_xor_sync(0xffffffffu, lg1, 1);
            lg2 += __shfl_xor_sync(0xffffffffu, lg2, 1);
            lg3 += __shfl_xor_sync(0xffffffffu, lg3, 1);

            if (k0 + 1 >= n) lg1 = -1e30f;
            if (k0 + 2 >= n) lg2 = -1e30f;
            if (k0 + 3 >= n) lg3 = -1e30f;

            float m = fmaxf(fmaxf(lg0, lg1), fmaxf(lg2, lg3));
            float w0 = __expf(lg0 - m);
            float w1 = __expf(lg1 - m);
            float w2 = __expf(lg2 - m);
            float w3 = __expf(lg3 - m);
            float pd = (w0 + w1) + (w2 + w3);
            float4 pa;
            pa.x = fmaf(w0, xv0.x, w1 * xv1.x) + fmaf(w2, xv2.x, w3 * xv3.x);
            pa.y = fmaf(w0, xv0.y, w1 * xv1.y) + fmaf(w2, xv2.y, w3 * xv3.y);
            pa.z = fmaf(w0, xv0.z, w1 * xv1.z) + fmaf(w2, xv2.z, w3 * xv3.z);
            pa.w = fmaf(w0, xv0.w, w1 * xv1.w) + fmaf(w2, xv2.w, w3 * xv3.w);

            float nm = fmaxf(mx, m);
            float a  = __expf(mx - nm);
            float b  = __expf(m - nm);
            dn = fmaf(dn, a, pd * b);
            ac.x = fmaf(ac.x, a, pa.x * b);
            ac.y = fmaf(ac.y, a, pa.y * b);
            ac.z = fmaf(ac.z, a, pa.z * b);
            ac.w = fmaf(ac.w, a, pa.w * b);
            mx = nm;
        }
    }
}

__global__ void __launch_bounds__(256) gat_row_kernel(const float* __restrict__ att,
                                                      const float* __restrict__ bias)
{
    __shared__ float s_mx[4][32], s_dn[4][32];
    __shared__ float s_ac[4][4][32];

    int w    = threadIdx.x >> 5;
    int lane = threadIdx.x & 31;
    int ridx = w >> 1;
    int half = w & 1;
    int row  = blockIdx.x * 4 + ridx;
    if (row >= GN) return;

    float4 attv = ((const float4*)att)[lane];
    float4 xrv  = ((const float4*)d_xr)[(size_t)row * 32 + lane];

    int e0 = d_rowstart[row], e1 = d_rowstart[row + 1];
    int mid = e0 + ((e1 - e0 + 1) >> 1);
    int s0 = half ? mid : e0;
    int s1 = half ? e1  : mid;

    const uint2* XL16 = (const uint2*)d_xl16;

    float mx, dn; float4 ac;
    gat_half(XL16, s0, s1, lane, xrv, attv, mx, dn, ac);

    if (half) {
        s_mx[ridx][lane] = mx;
        s_dn[ridx][lane] = dn;
        s_ac[ridx][0][lane] = ac.x;
        s_ac[ridx][1][lane] = ac.y;
        s_ac[ridx][2][lane] = ac.z;
        s_ac[ridx][3][lane] = ac.w;
    }
    __syncthreads();
    if (half) return;

    float mxB = s_mx[ridx][lane];
    float dnB = s_dn[ridx][lane];
    float nm = fmaxf(mx, mxB);
    float a  = __expf(mx - nm);
    float b  = __expf(mxB - nm);
    float dnT = fmaf(dn, a, dnB * b);
    float4 acT;
    acT.x = fmaf(ac.x, a, s_ac[ridx][0][lane] * b);
    acT.y = fmaf(ac.y, a, s_ac[ridx][1][lane] * b);
    acT.z = fmaf(ac.z, a, s_ac[ridx][2][lane] * b);
    acT.w = fmaf(ac.w, a, s_ac[ridx][3][lane] * b);

    float inv = 1.f / dnT;
    float4 bv = ((const float4*)bias)[lane];
    float4 o;
    o.x = fmaxf(fmaf(acT.x, inv, bv.x), 0.f);
    o.y = fmaxf(fmaf(acT.y, inv, bv.y), 0.f);
    o.z = fmaxf(fmaf(acT.z, inv, bv.z), 0.f);
    o.w = fmaxf(fmaf(acT.w, inv, bv.w), 0.f);
    ((float4*)d_h)[(size_t)row * 32 + lane] = o;
}

// ---------------- pooling (parallel + load-batched) ---------------------
#define PCHUNK 64
__global__ void pool_kernel(const void* __restrict__ batch) {
    int n0 = blockIdx.x * PCHUNK;
    int n1 = n0 + PCHUNK; if (n1 > GN) n1 = GN;
    int col = threadIdx.x;
    int is64 = d_is64;
    int curg = -1;
    float acc = 0.f;
    int run = 0;
    for (int n = n0; n < n1; n += 4) {
        int m = n1 - n; if (m > 4) m = 4;
        int   gid[4];
        float hv[4];
        #pragma unroll
        for (int k = 0; k < 4; k++) {
            if (k < m) {
                gid[k] = edge_at(batch, n + k, is64);
                hv[k]  = d_h[(size_t)(n + k) * 128 + col];
            }
        }
        #pragma unroll
        for (int k = 0; k < 4; k++) {
            if (k < m) {
                if (gid[k] != curg) {
                    if (curg >= 0) {
                        atomicAdd(&d_pool[curg * 128 + col], acc);
                        if (col == 0) atomicAdd(&d_cnt[curg], (float)run);
                    }
                    curg = gid[k]; acc = 0.f; run = 0;
                }
                acc += hv[k];
                run++;
            }
        }
    }
    if (curg >= 0) {
        atomicAdd(&d_pool[curg * 128 + col], acc);
        if (col == 0) atomicAdd(&d_cnt[curg], (float)run);
    }
}

// ---------------- classifier ----------------
__global__ void classifier_kernel(
    const float* __restrict__ Wc1, const float* __restrict__ bc1,
    const float* __restrict__ Wc2, const float* __restrict__ bc2,
    float* __restrict__ out)
{
    int g = threadIdx.x;
    if (g >= GG) return;
    float inv = 1.f / fmaxf(d_cnt[g], 1.f);
    float z[8];
    #pragma unroll
    for (int j = 0; j < 8; j++) {
        float s = 0.f;
        for (int k = 0; k < 128; k++)
            s += d_pool[g * 128 + k] * Wc1[j * 128 + k];
        s = s * inv + bc1[j];
        z[j] = fmaxf(s, 0.f);
    }
    float o = bc2[0];
    #pragma unroll
    for (int j = 0; j < 8; j++) o += z[j] * Wc2[j];
    out[g] = o;
}

// ---------------- launch ----------------
extern "C" void kernel_launch(void* const* d_in, const int* in_sizes, int n_in,
                              void* d_out, int out_size) {
    const float* x     = (const float*)d_in[0];
    const void*  ei    = d_in[1];
    const void*  batch = d_in[2];
    const float* Wl0 = (const float*)d_in[3];
    const float* bl0 = (const float*)d_in[4];
    const float* Wr0 = (const float*)d_in[5];
    const float* br0 = (const float*)d_in[6];
    const float* at0 = (const float*)d_in[7];
    const float* bi0 = (const float*)d_in[8];
    const float* Wl1 = (const float*)d_in[9];
    const float* bl1 = (const float*)d_in[10];
    const float* Wr1 = (const float*)d_in[11];
    const float* br1 = (const float*)d_in[12];
    const float* at1 = (const float*)d_in[13];
    const float* bi1 = (const float*)d_in[14];
    const float* Wc1 = (const float*)d_in[15];
    const float* bc1 = (const float*)d_in[16];
    const float* Wc2 = (const float*)d_in[17];
    const float* bc2 = (const float*)d_in[18];
    float* out = (float*)d_out;

    g_sh.init();

    const dim3 GEMM_GRID((GN + 127) / 128, 2);

    // Fork: gemm layer-0 on side stream, concurrent with CSR build.
    cudaEventRecord(g_sh.evFork, 0);
    cudaStreamWaitEvent(g_sh.s, g_sh.evFork, 0);
    gemm_kernel<<<GEMM_GRID, 256, 0, g_sh.s>>>(x, Wl0, bl0, Wr0, br0, 0);
    cudaEventRecord(g_sh.evJoin, g_sh.s);

    // CSR build chain on the main (capture) stream.
    init_kernel<<<(GN + 255) / 256, 256>>>((const int*)ei);
    hist_kernel<<<(EP + 255) / 256, 256>>>(ei);
    chunk_sum_kernel<<<NCH, 256>>>();
    tops_kernel<<<1, 128>>>();
    scan_apply_kernel<<<NCH, 512>>>();
    scatter_kernel<<<(EP + 255) / 256, 256>>>(ei);

    cudaStreamWaitEvent(0, g_sh.evJoin, 0);

    gat_row_kernel<<<(GN + 3) / 4, 256>>>(at0, bi0);
    gemm_kernel<<<GEMM_GRID, 256>>>(x, Wl1, bl1, Wr1, br1, 1);
    gat_row_kernel<<<(GN + 3) / 4, 256>>>(at1, bi1);

    pool_kernel<<<(GN + PCHUNK - 1) / PCHUNK, 128>>>(batch);
    classifier_kernel<<<1, 64>>>(Wc1, bc1, Wc2, bc2, out);
}